// round 3
// baseline (speedup 1.0000x reference)
#include <cuda_runtime.h>
#include <math.h>

#define BSZ   8
#define N0    4096
#define NMSG  4
#define NTOT  4100
#define CDIM  128
#define DH    32
#define ATT_SCALE 0.17677669529663687f  // 1/sqrt(32)

#define L1   256
#define LT1  260
#define HR1  16
#define WR1  16
#define L2   1024
#define LT2  1028
#define HR2  32
#define WR2  32

// ---------------- scratch (static device globals; no allocs) ----------------
__device__ float g_q[BSZ * NTOT * CDIM];       // Q projection [b][n][128]
__device__ float g_xk1[BSZ * LT1 * CDIM];      // branch1 tokens (pre/post LN in place)
__device__ float g_xk2[BSZ * LT2 * CDIM];
__device__ float g_kv1[BSZ * LT1 * CDIM];      // kv: o = t*64 + hh*32 + d
__device__ float g_kv2[BSZ * LT2 * CDIM];
__device__ float g_v1m[BSZ * LT1 * 64];        // v + dwconv(v) (msg: 2v), ch = hh*32+d
__device__ float g_v2m[BSZ * LT2 * 64];
__device__ float g_x12[BSZ * NTOT * CDIM];     // attention outputs, col = hg*32+d

enum { MODE_Q = 0, MODE_PATCH = 1, MODE_PLAIN = 2, MODE_PROJ = 3 };

// ---------------------------------------------------------------------------
// Generic tiled GEMM: Y[M,128] = X[M,K] @ W[128,K]^T + bias, with mode-specific
// X gather and epilogue. Block = 32 rows x 128 cols, BK=32, 256 threads,
// 4x4 register micro-tile per thread.
// ---------------------------------------------------------------------------
template <int MODE, int S>
__global__ void gemm128_kernel(const float* __restrict__ Acont,
                               const float* __restrict__ xsrc,
                               const float* __restrict__ msgsrc,
                               const float* __restrict__ Wt,
                               const float* __restrict__ bias,
                               float* __restrict__ out,
                               float* __restrict__ out2,
                               int M, int K, int Wr, int L, int Lt) {
    __shared__ float Xs[32][33];
    __shared__ float Ws[32][132];  // Ws[kk][col]

    const int tid  = threadIdx.x;
    const int trow = tid >> 5;   // 0..7  -> 4 rows each
    const int tcol = tid & 31;   // 0..31 -> 4 cols each
    const int rowBase = blockIdx.x * 32;

    float acc[4][4];
#pragma unroll
    for (int i = 0; i < 4; i++)
#pragma unroll
        for (int j = 0; j < 4; j++) acc[i][j] = 0.f;

    for (int k0 = 0; k0 < K; k0 += 32) {
        // load W chunk: coalesced along k
#pragma unroll
        for (int i = 0; i < 16; i++) {
            int idx = tid + i * 256;        // 0..4095
            int col = idx >> 5;
            int kk  = idx & 31;
            Ws[kk][col] = Wt[col * K + k0 + kk];
        }
        // load X chunk
#pragma unroll
        for (int i = 0; i < 4; i++) {
            int idx = tid + i * 256;        // 0..1023
            int r  = idx >> 5;
            int kk = idx & 31;
            int gr = rowBase + r;
            int k  = k0 + kk;
            float v = 0.f;
            if (gr < M) {
                if (MODE == MODE_Q) {
                    int b = gr / NTOT, n = gr - b * NTOT;
                    v = (n < N0) ? xsrc[(b * N0 + n) * CDIM + k]
                                 : msgsrc[(b * NMSG + (n - N0)) * CDIM + k];
                } else if (MODE == MODE_PATCH) {
                    const int SS = S * S;
                    int b = gr / L, l = gr - b * L;
                    int hr = l / Wr, wr = l - hr * Wr;
                    int c   = k / SS;
                    int pos = k - c * SS;
                    int ky = pos / S, kx = pos - ky * S;
                    int p = (hr * S + ky) * 64 + (wr * S + kx);
                    v = xsrc[(b * N0 + p) * CDIM + c];
                } else {  // PLAIN / PROJ: contiguous [M][128]
                    v = Acont[gr * CDIM + k];
                }
            }
            Xs[r][kk] = v;
        }
        __syncthreads();
#pragma unroll
        for (int kk = 0; kk < 32; kk++) {
            float a0 = Xs[trow * 4 + 0][kk];
            float a1 = Xs[trow * 4 + 1][kk];
            float a2 = Xs[trow * 4 + 2][kk];
            float a3 = Xs[trow * 4 + 3][kk];
            float b0 = Ws[kk][tcol * 4 + 0];
            float b1 = Ws[kk][tcol * 4 + 1];
            float b2 = Ws[kk][tcol * 4 + 2];
            float b3 = Ws[kk][tcol * 4 + 3];
            acc[0][0] += a0 * b0; acc[0][1] += a0 * b1; acc[0][2] += a0 * b2; acc[0][3] += a0 * b3;
            acc[1][0] += a1 * b0; acc[1][1] += a1 * b1; acc[1][2] += a1 * b2; acc[1][3] += a1 * b3;
            acc[2][0] += a2 * b0; acc[2][1] += a2 * b1; acc[2][2] += a2 * b2; acc[2][3] += a2 * b3;
            acc[3][0] += a3 * b0; acc[3][1] += a3 * b1; acc[3][2] += a3 * b2; acc[3][3] += a3 * b3;
        }
        __syncthreads();
    }

#pragma unroll
    for (int i = 0; i < 4; i++) {
        int gr = rowBase + trow * 4 + i;
        if (gr >= M) continue;
#pragma unroll
        for (int j = 0; j < 4; j++) {
            int col = tcol * 4 + j;
            float v = acc[i][j] + bias[col];
            if (MODE == MODE_PROJ) {
                int b = gr / NTOT, n = gr - b * NTOT;
                if (n < N0) {
                    v += xsrc[(b * N0 + n) * CDIM + col];
                    out[(b * N0 + n) * CDIM + col] = v;
                } else {
                    v += msgsrc[(b * NMSG + (n - N0)) * CDIM + col];
                    out2[(b * NMSG + (n - N0)) * CDIM + col] = v;
                }
            } else if (MODE == MODE_PATCH) {
                int b = gr / L, l = gr - b * L;
                out[(b * Lt + l) * CDIM + col] = v;
            } else {
                out[gr * CDIM + col] = v;
            }
        }
    }
}

// ---------------------------------------------------------------------------
// msg tokens through SR conv via summed weights: xk[b, L+n, o] = msg.Wsum^T + b
// ---------------------------------------------------------------------------
__global__ void msgr_kernel(const float* __restrict__ msg,
                            const float* __restrict__ srw,
                            const float* __restrict__ srb,
                            float* __restrict__ xk, int SS, int L, int Lt) {
    int o = threadIdx.x;  // 128
    int r = blockIdx.x;   // B*NMSG
    int b = r / NMSG, n = r - b * NMSG;
    float acc = srb[o];
    for (int c = 0; c < CDIM; c++) {
        const float* wp = srw + (o * CDIM + c) * SS;
        float ws = 0.f;
        for (int p = 0; p < SS; p++) ws += wp[p];
        acc += msg[(b * NMSG + n) * CDIM + c] * ws;
    }
    xk[(b * Lt + L + n) * CDIM + o] = acc;
}

// ---------------------------------------------------------------------------
// LayerNorm + exact GELU, in place. One block (128 threads) per row.
// ---------------------------------------------------------------------------
__global__ void ln_gelu_kernel(float* __restrict__ buf,
                               const float* __restrict__ g,
                               const float* __restrict__ be) {
    __shared__ float red[128];
    int r = blockIdx.x;
    int t = threadIdx.x;
    float v = buf[r * CDIM + t];
    red[t] = v;
    __syncthreads();
    for (int o = 64; o > 0; o >>= 1) {
        if (t < o) red[t] += red[t + o];
        __syncthreads();
    }
    float mu = red[0] * (1.f / 128.f);
    __syncthreads();
    float d = v - mu;
    red[t] = d * d;
    __syncthreads();
    for (int o = 64; o > 0; o >>= 1) {
        if (t < o) red[t] += red[t + o];
        __syncthreads();
    }
    float var = red[0] * (1.f / 128.f);
    float y = d * rsqrtf(var + 1e-5f) * g[t] + be[t];
    float gel = 0.5f * y * (1.f + erff(y * 0.70710678118654752f));
    buf[r * CDIM + t] = gel;
}

// ---------------------------------------------------------------------------
// v_mod: spatial tokens get v + depthwise3x3(v) + bias; msg tokens get 2v.
// ---------------------------------------------------------------------------
__global__ void vmod_kernel(const float* __restrict__ kv,
                            const float* __restrict__ lw,
                            const float* __restrict__ lb,
                            float* __restrict__ vm,
                            int Hr, int Wr, int L, int Lt) {
    int ch = threadIdx.x;  // 0..63
    int r  = blockIdx.x;   // B*Lt
    int b = r / Lt, l = r - b * Lt;
    float self = kv[(b * Lt + l) * CDIM + 64 + ch];
    float o;
    if (l < L) {
        int hr = l / Wr, wr = l - hr * Wr;
        float acc = lb[ch];
#pragma unroll
        for (int dy = 0; dy < 3; dy++) {
#pragma unroll
            for (int dx = 0; dx < 3; dx++) {
                int yy = hr + dy - 1, xx = wr + dx - 1;
                if (yy >= 0 && yy < Hr && xx >= 0 && xx < Wr)
                    acc += lw[ch * 9 + dy * 3 + dx] *
                           kv[(b * Lt + yy * Wr + xx) * CDIM + 64 + ch];
            }
        }
        o = self + acc;
    } else {
        o = 2.f * self;
    }
    vm[(b * Lt + l) * 64 + ch] = o;
}

// ---------------------------------------------------------------------------
// Flash-style attention. Block = (qtile of 64, head hh in {0,1}, batch b).
// 8 warps, each owns 8 query rows; K/V streamed in 64-key chunks.
// ---------------------------------------------------------------------------
__global__ void attn_kernel(const float* __restrict__ q,
                            const float* __restrict__ kv,
                            const float* __restrict__ vm,
                            float* __restrict__ out,
                            int Lt, int hgBase) {
    __shared__ float Qs[64][36];
    __shared__ float Ks[64][36];
    __shared__ float Vs[64][36];
    __shared__ float Ps[8][8][64];

    const int tid  = threadIdx.x;
    const int warp = tid >> 5;
    const int lane = tid & 31;
    const int qt = blockIdx.x, hh = blockIdx.y, b = blockIdx.z;
    const int hg = hgBase + hh;
    const int n0 = qt * 64;

    // load Q tile
#pragma unroll
    for (int i = 0; i < 8; i++) {
        int idx = tid + i * 256;
        int r = idx >> 5, d = idx & 31;
        int n = n0 + r;
        Qs[r][d] = (n < NTOT) ? q[(b * NTOT + n) * CDIM + hg * DH + d] : 0.f;
    }
    __syncthreads();

    float m_i[8], l_i[8], o_i[8];
#pragma unroll
    for (int i = 0; i < 8; i++) { m_i[i] = -1e30f; l_i[i] = 0.f; o_i[i] = 0.f; }

    const int nc = (Lt + 63) >> 6;
    for (int ci = 0; ci < nc; ci++) {
        int c0 = ci << 6;
#pragma unroll
        for (int i = 0; i < 8; i++) {
            int idx = tid + i * 256;
            int r = idx >> 5, d = idx & 31;
            int gl = c0 + r;
            float kk = 0.f, vv = 0.f;
            if (gl < Lt) {
                kk = kv[(b * Lt + gl) * CDIM + hh * DH + d];
                vv = vm[(b * Lt + gl) * 64 + hh * DH + d];
            }
            Ks[r][d] = kk;
            Vs[r][d] = vv;
        }
        __syncthreads();

        // scores: each lane handles columns lane and lane+32
        float s0[8], s1[8];
#pragma unroll
        for (int i = 0; i < 8; i++) { s0[i] = 0.f; s1[i] = 0.f; }
#pragma unroll
        for (int k4 = 0; k4 < 8; k4++) {
            float4 ka = *(const float4*)&Ks[lane][k4 * 4];
            float4 kb = *(const float4*)&Ks[lane + 32][k4 * 4];
#pragma unroll
            for (int i = 0; i < 8; i++) {
                float4 qv = *(const float4*)&Qs[warp * 8 + i][k4 * 4];
                s0[i] += qv.x * ka.x + qv.y * ka.y + qv.z * ka.z + qv.w * ka.w;
                s1[i] += qv.x * kb.x + qv.y * kb.y + qv.z * kb.z + qv.w * kb.w;
            }
        }
        bool v0 = (c0 + lane) < Lt;
        bool v1 = (c0 + lane + 32) < Lt;
#pragma unroll
        for (int i = 0; i < 8; i++) {
            float a = v0 ? s0[i] * ATT_SCALE : -1e30f;
            float c = v1 ? s1[i] * ATT_SCALE : -1e30f;
            float mx = fmaxf(a, c);
#pragma unroll
            for (int off = 16; off > 0; off >>= 1)
                mx = fmaxf(mx, __shfl_xor_sync(0xffffffffu, mx, off));
            float mnew = fmaxf(m_i[i], mx);
            float corr = __expf(m_i[i] - mnew);
            float p0 = __expf(a - mnew);
            float p1 = __expf(c - mnew);
            float ps = p0 + p1;
#pragma unroll
            for (int off = 16; off > 0; off >>= 1)
                ps += __shfl_xor_sync(0xffffffffu, ps, off);
            l_i[i] = l_i[i] * corr + ps;
            o_i[i] *= corr;
            m_i[i] = mnew;
            Ps[warp][i][lane] = p0;
            Ps[warp][i][lane + 32] = p1;
        }
        __syncwarp();

        // AV: o_i[i][lane] += sum_l P[i][l] * V[l][lane]
#pragma unroll
        for (int l4 = 0; l4 < 16; l4++) {
            float va = Vs[l4 * 4 + 0][lane];
            float vb = Vs[l4 * 4 + 1][lane];
            float vc = Vs[l4 * 4 + 2][lane];
            float vd = Vs[l4 * 4 + 3][lane];
#pragma unroll
            for (int i = 0; i < 8; i++) {
                float4 p = *(const float4*)&Ps[warp][i][l4 * 4];
                o_i[i] += p.x * va + p.y * vb + p.z * vc + p.w * vd;
            }
        }
        __syncthreads();
    }

#pragma unroll
    for (int i = 0; i < 8; i++) {
        int n = n0 + warp * 8 + i;
        if (n < NTOT)
            out[(b * NTOT + n) * CDIM + hg * DH + lane] = o_i[i] / l_i[i];
    }
}

// ---------------------------------------------------------------------------
extern "C" void kernel_launch(void* const* d_in, const int* in_sizes, int n_in,
                              void* d_out, int out_size) {
    const float* x     = (const float*)d_in[0];
    const float* msg   = (const float*)d_in[1];
    const float* Wq    = (const float*)d_in[2];
    const float* bq    = (const float*)d_in[3];
    const float* sr1w  = (const float*)d_in[4];
    const float* sr1b  = (const float*)d_in[5];
    const float* ln1g  = (const float*)d_in[6];
    const float* ln1b  = (const float*)d_in[7];
    const float* sr2w  = (const float*)d_in[8];
    const float* sr2b  = (const float*)d_in[9];
    const float* ln2g  = (const float*)d_in[10];
    const float* ln2b  = (const float*)d_in[11];
    const float* kv1w  = (const float*)d_in[12];
    const float* kv1b  = (const float*)d_in[13];
    const float* kv2w  = (const float*)d_in[14];
    const float* kv2b  = (const float*)d_in[15];
    const float* lc1w  = (const float*)d_in[16];
    const float* lc1b  = (const float*)d_in[17];
    const float* lc2w  = (const float*)d_in[18];
    const float* lc2b  = (const float*)d_in[19];
    const float* projw = (const float*)d_in[20];
    const float* projb = (const float*)d_in[21];
    (void)in_sizes; (void)n_in; (void)out_size;

    float* out_img = (float*)d_out;
    float* out_msg = out_img + (size_t)BSZ * N0 * CDIM;

    float *q, *xk1, *xk2, *kv1, *kv2, *v1m, *v2m, *x12;
    cudaGetSymbolAddress((void**)&q,   g_q);
    cudaGetSymbolAddress((void**)&xk1, g_xk1);
    cudaGetSymbolAddress((void**)&xk2, g_xk2);
    cudaGetSymbolAddress((void**)&kv1, g_kv1);
    cudaGetSymbolAddress((void**)&kv2, g_kv2);
    cudaGetSymbolAddress((void**)&v1m, g_v1m);
    cudaGetSymbolAddress((void**)&v2m, g_v2m);
    cudaGetSymbolAddress((void**)&x12, g_x12);

    // 1. Q projection: [B*4100,128] = concat(x,msg) @ Wq^T + bq
    gemm128_kernel<MODE_Q, 1><<<(BSZ * NTOT + 31) / 32, 256>>>(
        nullptr, x, msg, Wq, bq, q, nullptr, BSZ * NTOT, CDIM, 0, 0, 0);

    // 2. SR patch-embed convs (im2col GEMMs)
    gemm128_kernel<MODE_PATCH, 4><<<(BSZ * L1 + 31) / 32, 256>>>(
        nullptr, x, nullptr, sr1w, sr1b, xk1, nullptr, BSZ * L1, CDIM * 16, WR1, L1, LT1);
    gemm128_kernel<MODE_PATCH, 2><<<(BSZ * L2 + 31) / 32, 256>>>(
        nullptr, x, nullptr, sr2w, sr2b, xk2, nullptr, BSZ * L2, CDIM * 4, WR2, L2, LT2);

    // 3. msg tokens through summed SR weights
    msgr_kernel<<<BSZ * NMSG, 128>>>(msg, sr1w, sr1b, xk1, 16, L1, LT1);
    msgr_kernel<<<BSZ * NMSG, 128>>>(msg, sr2w, sr2b, xk2, 4, L2, LT2);

    // 4. LayerNorm + GELU (in place)
    ln_gelu_kernel<<<BSZ * LT1, 128>>>(xk1, ln1g, ln1b);
    ln_gelu_kernel<<<BSZ * LT2, 128>>>(xk2, ln2g, ln2b);

    // 5. KV projections
    gemm128_kernel<MODE_PLAIN, 1><<<(BSZ * LT1 + 31) / 32, 256>>>(
        xk1, nullptr, nullptr, kv1w, kv1b, kv1, nullptr, BSZ * LT1, CDIM, 0, 0, 0);
    gemm128_kernel<MODE_PLAIN, 1><<<(BSZ * LT2 + 31) / 32, 256>>>(
        xk2, nullptr, nullptr, kv2w, kv2b, kv2, nullptr, BSZ * LT2, CDIM, 0, 0, 0);

    // 6. V augmentation (depthwise conv / 2x for msg)
    vmod_kernel<<<BSZ * LT1, 64>>>(kv1, lc1w, lc1b, v1m, HR1, WR1, L1, LT1);
    vmod_kernel<<<BSZ * LT2, 64>>>(kv2, lc2w, lc2b, v2m, HR2, WR2, L2, LT2);

    // 7. attention, both branches, writing into g_x12 (col = hg*32 + d)
    {
        dim3 grid1((NTOT + 63) / 64, 2, BSZ);
        attn_kernel<<<grid1, 256>>>(q, kv1, v1m, x12, LT1, 0);
        dim3 grid2((NTOT + 63) / 64, 2, BSZ);
        attn_kernel<<<grid2, 256>>>(q, kv2, v2m, x12, LT2, 2);
    }

    // 8. output projection + residual, split write to d_out
    gemm128_kernel<MODE_PROJ, 1><<<(BSZ * NTOT + 31) / 32, 256>>>(
        x12, x, msg, projw, projb, out_img, out_msg, BSZ * NTOT, CDIM, 0, 0, 0);
}

// round 5
// speedup vs baseline: 1.7563x; 1.7563x over previous
#include <cuda_runtime.h>
#include <cuda_bf16.h>
#include <stdint.h>
#include <math.h>

#define BSZ   8
#define N0    4096
#define NMSG  4
#define NTOT  4100
#define CDIM  128
#define DH    32
#define ATT_SCALE 0.17677669529663687f  // 1/sqrt(32)

#define L1   256
#define LT1  260
#define HR1  16
#define WR1  16
#define L2   1024
#define LT2  1028
#define HR2  32
#define WR2  32

// ---------------- scratch (static device globals; no allocs) ----------------
__device__ float g_q[BSZ * NTOT * CDIM];       // Q projection [b][n][128]
__device__ float g_xk1[BSZ * LT1 * CDIM];      // branch1 tokens (pre/post LN in place)
__device__ float g_xk2[BSZ * LT2 * CDIM];
__device__ float g_kv1[BSZ * LT1 * CDIM];      // kv: o = t*64 + hh*32 + d
__device__ float g_kv2[BSZ * LT2 * CDIM];
__device__ float g_v1m[BSZ * LT1 * 64];        // v + dwconv(v) (msg: 2v), ch = hh*32+d
__device__ float g_v2m[BSZ * LT2 * 64];
__device__ float g_x12[BSZ * NTOT * CDIM];     // attention outputs, col = hg*32+d
__device__ float g_ws1[CDIM * CDIM];           // transposed summed SR weights [c][o]
__device__ float g_ws2[CDIM * CDIM];

enum { MODE_Q = 0, MODE_PATCH = 1, MODE_PLAIN = 2, MODE_PROJ = 3 };

// ---------------------------------------------------------------------------
// Generic tiled GEMM: Y[M,128] = X[M,K] @ W[128,K]^T + bias, with mode-specific
// X gather and epilogue. Block = 32 rows x 128 cols, BK=32, 256 threads,
// 4x4 register micro-tile per thread.
// ---------------------------------------------------------------------------
template <int MODE, int S>
__global__ void gemm128_kernel(const float* __restrict__ Acont,
                               const float* __restrict__ xsrc,
                               const float* __restrict__ msgsrc,
                               const float* __restrict__ Wt,
                               const float* __restrict__ bias,
                               float* __restrict__ out,
                               float* __restrict__ out2,
                               int M, int K, int Wr, int L, int Lt) {
    __shared__ float Xs[32][33];
    __shared__ float Ws[32][132];  // Ws[kk][col]

    const int tid  = threadIdx.x;
    const int trow = tid >> 5;   // 0..7  -> 4 rows each
    const int tcol = tid & 31;   // 0..31 -> 4 cols each
    const int rowBase = blockIdx.x * 32;

    float acc[4][4];
#pragma unroll
    for (int i = 0; i < 4; i++)
#pragma unroll
        for (int j = 0; j < 4; j++) acc[i][j] = 0.f;

    for (int k0 = 0; k0 < K; k0 += 32) {
        // load W chunk: coalesced along k
#pragma unroll
        for (int i = 0; i < 16; i++) {
            int idx = tid + i * 256;        // 0..4095
            int col = idx >> 5;
            int kk  = idx & 31;
            Ws[kk][col] = Wt[col * K + k0 + kk];
        }
        // load X chunk
#pragma unroll
        for (int i = 0; i < 4; i++) {
            int idx = tid + i * 256;        // 0..1023
            int r  = idx >> 5;
            int kk = idx & 31;
            int gr = rowBase + r;
            int k  = k0 + kk;
            float v = 0.f;
            if (gr < M) {
                if (MODE == MODE_Q) {
                    int b = gr / NTOT, n = gr - b * NTOT;
                    v = (n < N0) ? xsrc[(b * N0 + n) * CDIM + k]
                                 : msgsrc[(b * NMSG + (n - N0)) * CDIM + k];
                } else if (MODE == MODE_PATCH) {
                    const int SS = S * S;
                    int b = gr / L, l = gr - b * L;
                    int hr = l / Wr, wr = l - hr * Wr;
                    int c   = k / SS;
                    int pos = k - c * SS;
                    int ky = pos / S, kx = pos - ky * S;
                    int p = (hr * S + ky) * 64 + (wr * S + kx);
                    v = xsrc[(b * N0 + p) * CDIM + c];
                } else {  // PLAIN / PROJ: contiguous [M][128]
                    v = Acont[gr * CDIM + k];
                }
            }
            Xs[r][kk] = v;
        }
        __syncthreads();
#pragma unroll
        for (int kk = 0; kk < 32; kk++) {
            float a0 = Xs[trow * 4 + 0][kk];
            float a1 = Xs[trow * 4 + 1][kk];
            float a2 = Xs[trow * 4 + 2][kk];
            float a3 = Xs[trow * 4 + 3][kk];
            float b0 = Ws[kk][tcol * 4 + 0];
            float b1 = Ws[kk][tcol * 4 + 1];
            float b2 = Ws[kk][tcol * 4 + 2];
            float b3 = Ws[kk][tcol * 4 + 3];
            acc[0][0] += a0 * b0; acc[0][1] += a0 * b1; acc[0][2] += a0 * b2; acc[0][3] += a0 * b3;
            acc[1][0] += a1 * b0; acc[1][1] += a1 * b1; acc[1][2] += a1 * b2; acc[1][3] += a1 * b3;
            acc[2][0] += a2 * b0; acc[2][1] += a2 * b1; acc[2][2] += a2 * b2; acc[2][3] += a2 * b3;
            acc[3][0] += a3 * b0; acc[3][1] += a3 * b1; acc[3][2] += a3 * b2; acc[3][3] += a3 * b3;
        }
        __syncthreads();
    }

#pragma unroll
    for (int i = 0; i < 4; i++) {
        int gr = rowBase + trow * 4 + i;
        if (gr >= M) continue;
#pragma unroll
        for (int j = 0; j < 4; j++) {
            int col = tcol * 4 + j;
            float v = acc[i][j] + bias[col];
            if (MODE == MODE_PROJ) {
                int b = gr / NTOT, n = gr - b * NTOT;
                if (n < N0) {
                    v += xsrc[(b * N0 + n) * CDIM + col];
                    out[(b * N0 + n) * CDIM + col] = v;
                } else {
                    v += msgsrc[(b * NMSG + (n - N0)) * CDIM + col];
                    out2[(b * NMSG + (n - N0)) * CDIM + col] = v;
                }
            } else if (MODE == MODE_PATCH) {
                int b = gr / L, l = gr - b * L;
                out[(b * Lt + l) * CDIM + col] = v;
            } else {
                out[gr * CDIM + col] = v;
            }
        }
    }
}

// ---------------------------------------------------------------------------
// Precompute transposed summed SR weights: wsT[c][o] = sum_p srw[o][c][p]
// ---------------------------------------------------------------------------
__global__ void wsum_kernel(const float* __restrict__ srw,
                            float* __restrict__ wsT, int SS) {
    int idx = blockIdx.x * 256 + threadIdx.x;   // 0..16383
    if (idx >= CDIM * CDIM) return;
    int c = idx >> 7, o = idx & 127;
    const float* p = srw + (o * CDIM + c) * SS;
    float s = 0.f;
    for (int i = 0; i < SS; i++) s += p[i];
    wsT[c * CDIM + o] = s;
}

// ---------------------------------------------------------------------------
// msg tokens through summed SR weights (coalesced matvec over wsT)
// ---------------------------------------------------------------------------
__global__ void msgr2_kernel(const float* __restrict__ msg,
                             const float* __restrict__ wsT,
                             const float* __restrict__ srb,
                             float* __restrict__ xk, int L, int Lt) {
    __shared__ float mrow[CDIM];
    int r = blockIdx.x;   // B*NMSG
    int b = r / NMSG, n = r - b * NMSG;
    int o = threadIdx.x;  // 128
    mrow[o] = msg[(b * NMSG + n) * CDIM + o];
    __syncthreads();
    float a0 = srb[o], a1 = 0.f, a2 = 0.f, a3 = 0.f;
#pragma unroll 8
    for (int c = 0; c < CDIM; c += 4) {
        a0 += mrow[c + 0] * wsT[(c + 0) * CDIM + o];
        a1 += mrow[c + 1] * wsT[(c + 1) * CDIM + o];
        a2 += mrow[c + 2] * wsT[(c + 2) * CDIM + o];
        a3 += mrow[c + 3] * wsT[(c + 3) * CDIM + o];
    }
    xk[(b * Lt + L + n) * CDIM + o] = (a0 + a1) + (a2 + a3);
}

// ---------------------------------------------------------------------------
// LayerNorm + exact GELU, in place. One block (128 threads, 4 warps) per row.
// ---------------------------------------------------------------------------
__global__ void ln_gelu_kernel(float* __restrict__ buf,
                               const float* __restrict__ g,
                               const float* __restrict__ be) {
    __shared__ float sm1[4], sm2[4];
    int r = blockIdx.x;
    int t = threadIdx.x, w = t >> 5, lane = t & 31;
    float v = buf[r * CDIM + t];
    float s1 = v, s2 = v * v;
#pragma unroll
    for (int off = 16; off > 0; off >>= 1) {
        s1 += __shfl_xor_sync(0xffffffffu, s1, off);
        s2 += __shfl_xor_sync(0xffffffffu, s2, off);
    }
    if (lane == 0) { sm1[w] = s1; sm2[w] = s2; }
    __syncthreads();
    s1 = (sm1[0] + sm1[1]) + (sm1[2] + sm1[3]);
    s2 = (sm2[0] + sm2[1]) + (sm2[2] + sm2[3]);
    float mu  = s1 * (1.f / 128.f);
    float var = fmaxf(s2 * (1.f / 128.f) - mu * mu, 0.f);
    float y = (v - mu) * rsqrtf(var + 1e-5f) * g[t] + be[t];
    buf[r * CDIM + t] = 0.5f * y * (1.f + erff(y * 0.70710678118654752f));
}

// ---------------------------------------------------------------------------
// v_mod: spatial tokens get v + depthwise3x3(v) + bias; msg tokens get 2v.
// ---------------------------------------------------------------------------
__global__ void vmod_kernel(const float* __restrict__ kv,
                            const float* __restrict__ lw,
                            const float* __restrict__ lb,
                            float* __restrict__ vm,
                            int Hr, int Wr, int L, int Lt) {
    int ch = threadIdx.x;  // 0..63
    int r  = blockIdx.x;   // B*Lt
    int b = r / Lt, l = r - b * Lt;
    float self = kv[(b * Lt + l) * CDIM + 64 + ch];
    float o;
    if (l < L) {
        int hr = l / Wr, wr = l - hr * Wr;
        float acc = lb[ch];
#pragma unroll
        for (int dy = 0; dy < 3; dy++) {
#pragma unroll
            for (int dx = 0; dx < 3; dx++) {
                int yy = hr + dy - 1, xx = wr + dx - 1;
                if (yy >= 0 && yy < Hr && xx >= 0 && xx < Wr)
                    acc += lw[ch * 9 + dy * 3 + dx] *
                           kv[(b * Lt + yy * Wr + xx) * CDIM + 64 + ch];
            }
        }
        o = self + acc;
    } else {
        o = 2.f * self;
    }
    vm[(b * Lt + l) * 64 + ch] = o;
}

// ---------------------------------------------------------------------------
// bf16 tensor-core flash attention (mma.sync.m16n8k16, fp32 accumulate).
// Block = (qtile of 64, hg in 0..3, batch). 4 warps, each owns 16 query rows.
// blockIdx.y = hg; branch = hg>>1, head-in-branch = hg&1.
// ---------------------------------------------------------------------------
__device__ __forceinline__ void mma_bf16(float c[4],
                                         uint32_t a0, uint32_t a1, uint32_t a2, uint32_t a3,
                                         uint32_t b0, uint32_t b1) {
    asm volatile(
        "mma.sync.aligned.m16n8k16.row.col.f32.bf16.bf16.f32 "
        "{%0,%1,%2,%3}, {%4,%5,%6,%7}, {%8,%9}, {%0,%1,%2,%3};"
        : "+f"(c[0]), "+f"(c[1]), "+f"(c[2]), "+f"(c[3])
        : "r"(a0), "r"(a1), "r"(a2), "r"(a3), "r"(b0), "r"(b1));
}

__device__ __forceinline__ uint32_t pack_bf16x2(float lo, float hi) {
    __nv_bfloat162 h = __floats2bfloat162_rn(lo, hi);
    return *reinterpret_cast<uint32_t*>(&h);
}

__global__ void attn_mma_kernel(const float* __restrict__ q,
                                const float* __restrict__ kv1,
                                const float* __restrict__ vm1,
                                const float* __restrict__ kv2,
                                const float* __restrict__ vm2,
                                float* __restrict__ out) {
    __shared__ __nv_bfloat16 Qs[64][40];   // stride 40 -> conflict-free frag loads
    __shared__ __nv_bfloat16 Ks[64][40];
    __shared__ __nv_bfloat16 Vt[32][72];   // V transposed [d][key]

    const int tid  = threadIdx.x;
    const int warp = tid >> 5;
    const int lane = tid & 31;
    const int qt = blockIdx.x, hg = blockIdx.y, b = blockIdx.z;
    const int br = hg >> 1, hh = hg & 1;
    const float* kvp = br ? kv2 : kv1;
    const float* vmp = br ? vm2 : vm1;
    const int Lt = br ? LT2 : LT1;
    const int n0 = qt * 64;

    // load Q tile (scaled) -> bf16
#pragma unroll
    for (int i = 0; i < 16; i++) {
        int idx = tid + i * 128;
        int r = idx >> 5, d = idx & 31;
        int n = n0 + r;
        float v = (n < NTOT) ? q[((size_t)b * NTOT + n) * CDIM + hg * DH + d] * ATT_SCALE : 0.f;
        Qs[r][d] = __float2bfloat16(v);
    }
    __syncthreads();

    const int r0 = warp * 16 + (lane >> 2);
    const int m2 = (lane & 3) * 2;

    // Q A-fragments (K=32 -> 2 k-steps), loaded once
    uint32_t qa[2][4];
#pragma unroll
    for (int kt = 0; kt < 2; kt++) {
        qa[kt][0] = *(const uint32_t*)&Qs[r0][kt * 16 + m2];
        qa[kt][1] = *(const uint32_t*)&Qs[r0 + 8][kt * 16 + m2];
        qa[kt][2] = *(const uint32_t*)&Qs[r0][kt * 16 + m2 + 8];
        qa[kt][3] = *(const uint32_t*)&Qs[r0 + 8][kt * 16 + m2 + 8];
    }

    float o[4][4];
#pragma unroll
    for (int i = 0; i < 4; i++)
#pragma unroll
        for (int j = 0; j < 4; j++) o[i][j] = 0.f;
    float m0 = -1e30f, m1 = -1e30f, l0 = 0.f, l1 = 0.f;

    const int nc = (Lt + 63) >> 6;
    for (int ci = 0; ci < nc; ci++) {
        const int c0 = ci << 6;
        __syncthreads();  // previous chunk's smem reads done
#pragma unroll
        for (int i = 0; i < 16; i++) {
            int idx = tid + i * 128;
            int r = idx >> 5, d = idx & 31;
            int gl = c0 + r;
            float kk = 0.f, vv = 0.f;
            if (gl < Lt) {
                kk = kvp[((size_t)b * Lt + gl) * CDIM + hh * DH + d];
                vv = vmp[((size_t)b * Lt + gl) * 64 + hh * DH + d];
            }
            Ks[r][d] = __float2bfloat16(kk);
            Vt[d][r] = __float2bfloat16(vv);
        }
        __syncthreads();

        // S = Q @ K^T : 8 n-tiles (8 cols each) x 2 k-steps
        float s[8][4];
#pragma unroll
        for (int nt = 0; nt < 8; nt++) { s[nt][0] = s[nt][1] = s[nt][2] = s[nt][3] = 0.f; }
#pragma unroll
        for (int nt = 0; nt < 8; nt++) {
#pragma unroll
            for (int kt = 0; kt < 2; kt++) {
                uint32_t b0 = *(const uint32_t*)&Ks[nt * 8 + (lane >> 2)][kt * 16 + m2];
                uint32_t b1 = *(const uint32_t*)&Ks[nt * 8 + (lane >> 2)][kt * 16 + m2 + 8];
                mma_bf16(s[nt], qa[kt][0], qa[kt][1], qa[kt][2], qa[kt][3], b0, b1);
            }
        }

        // mask + online softmax (rows r0 -> c0/c1, r0+8 -> c2/c3)
        float mx0 = m0, mx1 = m1;
#pragma unroll
        for (int nt = 0; nt < 8; nt++) {
            int gc = c0 + nt * 8 + m2;
            if (gc >= Lt)     { s[nt][0] = -1e30f; s[nt][2] = -1e30f; }
            if (gc + 1 >= Lt) { s[nt][1] = -1e30f; s[nt][3] = -1e30f; }
            mx0 = fmaxf(mx0, fmaxf(s[nt][0], s[nt][1]));
            mx1 = fmaxf(mx1, fmaxf(s[nt][2], s[nt][3]));
        }
        mx0 = fmaxf(mx0, __shfl_xor_sync(0xffffffffu, mx0, 1));
        mx0 = fmaxf(mx0, __shfl_xor_sync(0xffffffffu, mx0, 2));
        mx1 = fmaxf(mx1, __shfl_xor_sync(0xffffffffu, mx1, 1));
        mx1 = fmaxf(mx1, __shfl_xor_sync(0xffffffffu, mx1, 2));
        float corr0 = __expf(m0 - mx0), corr1 = __expf(m1 - mx1);
        m0 = mx0; m1 = mx1;

        float ls0 = 0.f, ls1 = 0.f;
#pragma unroll
        for (int nt = 0; nt < 8; nt++) {
            s[nt][0] = __expf(s[nt][0] - m0);
            s[nt][1] = __expf(s[nt][1] - m0);
            s[nt][2] = __expf(s[nt][2] - m1);
            s[nt][3] = __expf(s[nt][3] - m1);
            ls0 += s[nt][0] + s[nt][1];
            ls1 += s[nt][2] + s[nt][3];
        }
        ls0 += __shfl_xor_sync(0xffffffffu, ls0, 1);
        ls0 += __shfl_xor_sync(0xffffffffu, ls0, 2);
        ls1 += __shfl_xor_sync(0xffffffffu, ls1, 1);
        ls1 += __shfl_xor_sync(0xffffffffu, ls1, 2);
        l0 = l0 * corr0 + ls0;
        l1 = l1 * corr1 + ls1;
#pragma unroll
        for (int nt = 0; nt < 4; nt++) {
            o[nt][0] *= corr0; o[nt][1] *= corr0;
            o[nt][2] *= corr1; o[nt][3] *= corr1;
        }

        // O += P @ V : P C-frags repack directly into A-frags (FA2 trick)
#pragma unroll
        for (int kt = 0; kt < 4; kt++) {
            uint32_t a0 = pack_bf16x2(s[2 * kt][0],     s[2 * kt][1]);
            uint32_t a1 = pack_bf16x2(s[2 * kt][2],     s[2 * kt][3]);
            uint32_t a2 = pack_bf16x2(s[2 * kt + 1][0], s[2 * kt + 1][1]);
            uint32_t a3 = pack_bf16x2(s[2 * kt + 1][2], s[2 * kt + 1][3]);
#pragma unroll
            for (int nt = 0; nt < 4; nt++) {
                uint32_t b0 = *(const uint32_t*)&Vt[nt * 8 + (lane >> 2)][kt * 16 + m2];
                uint32_t b1 = *(const uint32_t*)&Vt[nt * 8 + (lane >> 2)][kt * 16 + m2 + 8];
                mma_bf16(o[nt], a0, a1, a2, a3, b0, b1);
            }
        }
    }

    float inv0 = 1.f / l0, inv1 = 1.f / l1;
    int nr0 = n0 + r0, nr1 = nr0 + 8;
#pragma unroll
    for (int nt = 0; nt < 4; nt++) {
        int col = hg * DH + nt * 8 + m2;
        if (nr0 < NTOT)
            *(float2*)&out[((size_t)b * NTOT + nr0) * CDIM + col] =
                make_float2(o[nt][0] * inv0, o[nt][1] * inv0);
        if (nr1 < NTOT)
            *(float2*)&out[((size_t)b * NTOT + nr1) * CDIM + col] =
                make_float2(o[nt][2] * inv1, o[nt][3] * inv1);
    }
}

// ---------------------------------------------------------------------------
extern "C" void kernel_launch(void* const* d_in, const int* in_sizes, int n_in,
                              void* d_out, int out_size) {
    const float* x     = (const float*)d_in[0];
    const float* msg   = (const float*)d_in[1];
    const float* Wq    = (const float*)d_in[2];
    const float* bq    = (const float*)d_in[3];
    const float* sr1w  = (const float*)d_in[4];
    const float* sr1b  = (const float*)d_in[5];
    const float* ln1g  = (const float*)d_in[6];
    const float* ln1b  = (const float*)d_in[7];
    const float* sr2w  = (const float*)d_in[8];
    const float* sr2b  = (const float*)d_in[9];
    const float* ln2g  = (const float*)d_in[10];
    const float* ln2b  = (const float*)d_in[11];
    const float* kv1w  = (const float*)d_in[12];
    const float* kv1b  = (const float*)d_in[13];
    const float* kv2w  = (const float*)d_in[14];
    const float* kv2b  = (const float*)d_in[15];
    const float* lc1w  = (const float*)d_in[16];
    const float* lc1b  = (const float*)d_in[17];
    const float* lc2w  = (const float*)d_in[18];
    const float* lc2b  = (const float*)d_in[19];
    const float* projw = (const float*)d_in[20];
    const float* projb = (const float*)d_in[21];
    (void)in_sizes; (void)n_in; (void)out_size;

    float* out_img = (float*)d_out;
    float* out_msg = out_img + (size_t)BSZ * N0 * CDIM;

    float *q, *xk1, *xk2, *kv1, *kv2, *v1m, *v2m, *x12, *ws1, *ws2;
    cudaGetSymbolAddress((void**)&q,   g_q);
    cudaGetSymbolAddress((void**)&xk1, g_xk1);
    cudaGetSymbolAddress((void**)&xk2, g_xk2);
    cudaGetSymbolAddress((void**)&kv1, g_kv1);
    cudaGetSymbolAddress((void**)&kv2, g_kv2);
    cudaGetSymbolAddress((void**)&v1m, g_v1m);
    cudaGetSymbolAddress((void**)&v2m, g_v2m);
    cudaGetSymbolAddress((void**)&x12, g_x12);
    cudaGetSymbolAddress((void**)&ws1, g_ws1);
    cudaGetSymbolAddress((void**)&ws2, g_ws2);

    // 0. summed SR weights (transposed) for msg-token pass-through
    wsum_kernel<<<(CDIM * CDIM + 255) / 256, 256>>>(sr1w, ws1, 16);
    wsum_kernel<<<(CDIM * CDIM + 255) / 256, 256>>>(sr2w, ws2, 4);

    // 1. Q projection: [B*4100,128] = concat(x,msg) @ Wq^T + bq
    gemm128_kernel<MODE_Q, 1><<<(BSZ * NTOT + 31) / 32, 256>>>(
        nullptr, x, msg, Wq, bq, q, nullptr, BSZ * NTOT, CDIM, 0, 0, 0);

    // 2. SR patch-embed convs (im2col GEMMs)
    gemm128_kernel<MODE_PATCH, 4><<<(BSZ * L1 + 31) / 32, 256>>>(
        nullptr, x, nullptr, sr1w, sr1b, xk1, nullptr, BSZ * L1, CDIM * 16, WR1, L1, LT1);
    gemm128_kernel<MODE_PATCH, 2><<<(BSZ * L2 + 31) / 32, 256>>>(
        nullptr, x, nullptr, sr2w, sr2b, xk2, nullptr, BSZ * L2, CDIM * 4, WR2, L2, LT2);

    // 3. msg tokens through summed SR weights
    msgr2_kernel<<<BSZ * NMSG, 128>>>(msg, ws1, sr1b, xk1, L1, LT1);
    msgr2_kernel<<<BSZ * NMSG, 128>>>(msg, ws2, sr2b, xk2, L2, LT2);

    // 4. LayerNorm + GELU (in place)
    ln_gelu_kernel<<<BSZ * LT1, 128>>>(xk1, ln1g, ln1b);
    ln_gelu_kernel<<<BSZ * LT2, 128>>>(xk2, ln2g, ln2b);

    // 5. KV projections
    gemm128_kernel<MODE_PLAIN, 1><<<(BSZ * LT1 + 31) / 32, 256>>>(
        xk1, nullptr, nullptr, kv1w, kv1b, kv1, nullptr, BSZ * LT1, CDIM, 0, 0, 0);
    gemm128_kernel<MODE_PLAIN, 1><<<(BSZ * LT2 + 31) / 32, 256>>>(
        xk2, nullptr, nullptr, kv2w, kv2b, kv2, nullptr, BSZ * LT2, CDIM, 0, 0, 0);

    // 6. V augmentation (depthwise conv / 2x for msg)
    vmod_kernel<<<BSZ * LT1, 64>>>(kv1, lc1w, lc1b, v1m, HR1, WR1, L1, LT1);
    vmod_kernel<<<BSZ * LT2, 64>>>(kv2, lc2w, lc2b, v2m, HR2, WR2, L2, LT2);

    // 7. attention: both branches + both heads in one launch (hg = blockIdx.y)
    {
        dim3 grid((NTOT + 63) / 64, 4, BSZ);
        attn_mma_kernel<<<grid, 128>>>(q, kv1, v1m, kv2, v2m, x12);
    }

    // 8. output projection + residual, split write to d_out
    gemm128_kernel<MODE_PROJ, 1><<<(BSZ * NTOT + 31) / 32, 256>>>(
        x12, x, msg, projw, projb, out_img, out_msg, BSZ * NTOT, CDIM, 0, 0, 0);
}

// round 7
// speedup vs baseline: 4.0566x; 2.3097x over previous
#include <cuda_runtime.h>
#include <cuda_bf16.h>
#include <stdint.h>
#include <math.h>

#define BSZ   8
#define N0    4096
#define NMSG  4
#define NTOT  4100
#define CDIM  128
#define DH    32
#define ATT_SCALE 0.17677669529663687f  // 1/sqrt(32)

#define L1   256
#define LT1  260
#define HR1  16
#define WR1  16
#define L2   1024
#define LT2  1028
#define HR2  32
#define WR2  32

// ---------------- scratch (static device globals; no allocs) ----------------
__device__ float g_xk1[BSZ * LT1 * CDIM];      // branch tokens pre-LN (fp32)
__device__ float g_xk2[BSZ * LT2 * CDIM];
__device__ float g_kv1[BSZ * LT1 * CDIM];      // kv: o = t*64 + hh*32 + d (fp32)
__device__ float g_kv2[BSZ * LT2 * CDIM];
__device__ float g_v1m[BSZ * LT1 * 64];        // v + dwconv(v) (msg: 2v)
__device__ float g_v2m[BSZ * LT2 * 64];
__device__ float g_ws1[CDIM * CDIM];           // transposed summed SR weights [c][o]
__device__ float g_ws2[CDIM * CDIM];

// bf16 activations
__device__ __nv_bfloat16 g_xb[BSZ * N0 * CDIM];     // x in bf16
__device__ __nv_bfloat16 g_msgb[BSZ * NMSG * CDIM];
__device__ __nv_bfloat16 g_qb[BSZ * NTOT * CDIM];   // Q (pre-scaled)
__device__ __nv_bfloat16 g_xk1b[BSZ * LT1 * CDIM];  // post LN+GELU
__device__ __nv_bfloat16 g_xk2b[BSZ * LT2 * CDIM];
__device__ __nv_bfloat16 g_x12b[BSZ * NTOT * CDIM]; // attention outputs

// bf16 weights (pre-converted / reordered)
__device__ __nv_bfloat16 g_wqb[CDIM * CDIM];
__device__ __nv_bfloat16 g_sr1wb[CDIM * CDIM * 16]; // [o][pos*128+c]
__device__ __nv_bfloat16 g_sr2wb[CDIM * CDIM * 4];
__device__ __nv_bfloat16 g_kv1wb[CDIM * CDIM];
__device__ __nv_bfloat16 g_kv2wb[CDIM * CDIM];
__device__ __nv_bfloat16 g_projwb[CDIM * CDIM];

enum { MODE_Q = 0, MODE_PATCH = 1, MODE_PLAIN = 2, MODE_PROJ = 3 };

// ---------------------------------------------------------------------------
__device__ __forceinline__ void mma_bf16(float c[4],
                                         uint32_t a0, uint32_t a1, uint32_t a2, uint32_t a3,
                                         uint32_t b0, uint32_t b1) {
    asm volatile(
        "mma.sync.aligned.m16n8k16.row.col.f32.bf16.bf16.f32 "
        "{%0,%1,%2,%3}, {%4,%5,%6,%7}, {%8,%9}, {%0,%1,%2,%3};"
        : "+f"(c[0]), "+f"(c[1]), "+f"(c[2]), "+f"(c[3])
        : "r"(a0), "r"(a1), "r"(a2), "r"(a3), "r"(b0), "r"(b1));
}

__device__ __forceinline__ uint32_t pack_bf16x2(float lo, float hi) {
    __nv_bfloat162 h = __floats2bfloat162_rn(lo, hi);
    return *reinterpret_cast<uint32_t*>(&h);
}

// ---------------------------------------------------------------------------
// Unified bf16 tensor-core GEMM: Y[M,128] = X[M,K] @ W[128,K]^T + bias.
// Tile 64 rows x 128 cols, 256 threads / 8 warps, K chunk = 32.
// Warp w: rows 16*(w&3).., cols 64*(w>>2)..  (m16n8k16, fp32 accum)
// MODE selects X gather + epilogue. For PATCH, K-index = pos*128 + c
// (weights pre-reordered) so each 32-chunk is a contiguous channel run.
// ---------------------------------------------------------------------------
template <int MODE, int S>
__global__ void bgemm_kernel(const __nv_bfloat16* __restrict__ Ab,
                             const __nv_bfloat16* __restrict__ xb,
                             const __nv_bfloat16* __restrict__ msgb,
                             const __nv_bfloat16* __restrict__ Wb,
                             const float* __restrict__ bias,
                             float* __restrict__ outf,
                             float* __restrict__ out2f,
                             __nv_bfloat16* __restrict__ outb,
                             const float* __restrict__ resx,
                             const float* __restrict__ resmsg,
                             int M, int K, int Wr, int L, int Lt) {
    __shared__ __nv_bfloat16 Xs[64][40];
    __shared__ __nv_bfloat16 Wsm[128][40];

    const int tid  = threadIdx.x;
    const int warp = tid >> 5;
    const int lane = tid & 31;
    const int mrow = (warp & 3) * 16;
    const int colBase = (warp >> 2) * 64;
    const int rowBase = blockIdx.x * 64;

    // per-thread X load assignment: 4 threads per row, 8 bf16 each
    const int lrow = tid >> 2;
    const int koff = (tid & 3) * 8;
    const int gr = rowBase + lrow;
    const bool valid = gr < M;

    const __nv_bfloat16* srcRow = nullptr;
    int pb = 0, phr = 0, pwr = 0;
    if (MODE == MODE_Q) {
        if (valid) {
            int b = gr / NTOT, n = gr - b * NTOT;
            srcRow = (n < N0) ? xb + ((size_t)b * N0 + n) * CDIM
                              : msgb + ((size_t)b * NMSG + (n - N0)) * CDIM;
        }
    } else if (MODE == MODE_PATCH) {
        if (valid) { pb = gr / L; int l = gr - pb * L; phr = l / Wr; pwr = l - phr * Wr; }
    } else {
        if (valid) srcRow = Ab + (size_t)gr * CDIM;
    }

    const int fr = lane >> 2;
    const int m2 = (lane & 3) * 2;

    float c[8][4];
#pragma unroll
    for (int nt = 0; nt < 8; nt++) { c[nt][0] = c[nt][1] = c[nt][2] = c[nt][3] = 0.f; }

    for (int k0 = 0; k0 < K; k0 += 32) {
        uint4 xv = make_uint4(0u, 0u, 0u, 0u);
        if (valid) {
            if (MODE == MODE_PATCH) {
                int pos = k0 >> 7;  // chunk of 32 lies within one pos block
                int ky = (S == 4) ? (pos >> 2) : (pos >> 1);
                int kx = (S == 4) ? (pos & 3) : (pos & 1);
                int p = (phr * S + ky) * 64 + pwr * S + kx;
                xv = *(const uint4*)(xb + ((size_t)pb * N0 + p) * CDIM + (k0 & 127) + koff);
            } else {
                xv = *(const uint4*)(srcRow + k0 + koff);
            }
        }
        *(uint4*)&Xs[lrow][koff] = xv;
        {
            const __nv_bfloat16* wp = Wb + (size_t)(tid >> 1) * K + k0 + (tid & 1) * 16;
            *(uint4*)&Wsm[tid >> 1][(tid & 1) * 16]     = *(const uint4*)wp;
            *(uint4*)&Wsm[tid >> 1][(tid & 1) * 16 + 8] = *(const uint4*)(wp + 8);
        }
        __syncthreads();

#pragma unroll
        for (int kt = 0; kt < 2; kt++) {
            uint32_t a0 = *(const uint32_t*)&Xs[mrow + fr][kt * 16 + m2];
            uint32_t a1 = *(const uint32_t*)&Xs[mrow + fr + 8][kt * 16 + m2];
            uint32_t a2 = *(const uint32_t*)&Xs[mrow + fr][kt * 16 + m2 + 8];
            uint32_t a3 = *(const uint32_t*)&Xs[mrow + fr + 8][kt * 16 + m2 + 8];
#pragma unroll
            for (int nt = 0; nt < 8; nt++) {
                uint32_t b0 = *(const uint32_t*)&Wsm[colBase + nt * 8 + fr][kt * 16 + m2];
                uint32_t b1 = *(const uint32_t*)&Wsm[colBase + nt * 8 + fr][kt * 16 + m2 + 8];
                mma_bf16(c[nt], a0, a1, a2, a3, b0, b1);
            }
        }
        __syncthreads();
    }

    // epilogue
    const int r0 = rowBase + mrow + fr;
    const int r1 = r0 + 8;
#pragma unroll
    for (int nt = 0; nt < 8; nt++) {
        int col = colBase + nt * 8 + m2;
        float bb0 = bias[col], bb1 = bias[col + 1];
        float v00 = c[nt][0] + bb0, v01 = c[nt][1] + bb1;   // row r0
        float v10 = c[nt][2] + bb0, v11 = c[nt][3] + bb1;   // row r1

        if (MODE == MODE_Q) {
            if (r0 < M) *(uint32_t*)&outb[(size_t)r0 * CDIM + col] =
                pack_bf16x2(v00 * ATT_SCALE, v01 * ATT_SCALE);
            if (r1 < M) *(uint32_t*)&outb[(size_t)r1 * CDIM + col] =
                pack_bf16x2(v10 * ATT_SCALE, v11 * ATT_SCALE);
        } else if (MODE == MODE_PATCH) {
            if (r0 < M) {
                int b = r0 / L, l = r0 - b * L;
                *(float2*)&outf[((size_t)b * Lt + l) * CDIM + col] = make_float2(v00, v01);
            }
            if (r1 < M) {
                int b = r1 / L, l = r1 - b * L;
                *(float2*)&outf[((size_t)b * Lt + l) * CDIM + col] = make_float2(v10, v11);
            }
        } else if (MODE == MODE_PLAIN) {
            if (r0 < M) *(float2*)&outf[(size_t)r0 * CDIM + col] = make_float2(v00, v01);
            if (r1 < M) *(float2*)&outf[(size_t)r1 * CDIM + col] = make_float2(v10, v11);
        } else {  // MODE_PROJ: residual + split write
            if (r0 < M) {
                int b = r0 / NTOT, n = r0 - b * NTOT;
                if (n < N0) {
                    size_t o = ((size_t)b * N0 + n) * CDIM + col;
                    *(float2*)&outf[o] = make_float2(v00 + resx[o], v01 + resx[o + 1]);
                } else {
                    size_t o = ((size_t)b * NMSG + (n - N0)) * CDIM + col;
                    *(float2*)&out2f[o] = make_float2(v00 + resmsg[o], v01 + resmsg[o + 1]);
                }
            }
            if (r1 < M) {
                int b = r1 / NTOT, n = r1 - b * NTOT;
                if (n < N0) {
                    size_t o = ((size_t)b * N0 + n) * CDIM + col;
                    *(float2*)&outf[o] = make_float2(v10 + resx[o], v11 + resx[o + 1]);
                } else {
                    size_t o = ((size_t)b * NMSG + (n - N0)) * CDIM + col;
                    *(float2*)&out2f[o] = make_float2(v10 + resmsg[o], v11 + resmsg[o + 1]);
                }
            }
        }
    }
}

// ---------------------------------------------------------------------------
// fp32 -> bf16 elementwise
// ---------------------------------------------------------------------------
__global__ void f2b_kernel(const float* __restrict__ in,
                           __nv_bfloat16* __restrict__ out, int n) {
    int i = blockIdx.x * 256 + threadIdx.x;
    if (i < n) out[i] = __float2bfloat16(in[i]);
}

// SR conv weight reorder: dst[o][pos*128+c] = src[o][c][pos], bf16
__global__ void wreorder_kernel(const float* __restrict__ src,
                                __nv_bfloat16* __restrict__ dst, int SS) {
    int idx = blockIdx.x * 256 + threadIdx.x;
    int tot = CDIM * CDIM * SS;
    if (idx >= tot) return;
    int o = idx / (CDIM * SS);
    int rem = idx - o * (CDIM * SS);
    int cch = rem / SS;
    int pos = rem - cch * SS;
    dst[(size_t)o * (CDIM * SS) + pos * CDIM + cch] = __float2bfloat16(src[idx]);
}

// ---------------------------------------------------------------------------
// Precompute transposed summed SR weights: wsT[c][o] = sum_p srw[o][c][p]
// ---------------------------------------------------------------------------
__global__ void wsum_kernel(const float* __restrict__ srw,
                            float* __restrict__ wsT, int SS) {
    int idx = blockIdx.x * 256 + threadIdx.x;
    if (idx >= CDIM * CDIM) return;
    int c = idx >> 7, o = idx & 127;
    const float* p = srw + (o * CDIM + c) * SS;
    float s = 0.f;
    for (int i = 0; i < SS; i++) s += p[i];
    wsT[c * CDIM + o] = s;
}

// ---------------------------------------------------------------------------
// msg tokens through summed SR weights (coalesced matvec over wsT)
// ---------------------------------------------------------------------------
__global__ void msgr2_kernel(const float* __restrict__ msg,
                             const float* __restrict__ wsT,
                             const float* __restrict__ srb,
                             float* __restrict__ xk, int L, int Lt) {
    __shared__ float mrow[CDIM];
    int r = blockIdx.x;   // B*NMSG
    int b = r / NMSG, n = r - b * NMSG;
    int o = threadIdx.x;  // 128
    mrow[o] = msg[(b * NMSG + n) * CDIM + o];
    __syncthreads();
    float a0 = srb[o], a1 = 0.f, a2 = 0.f, a3 = 0.f;
#pragma unroll 8
    for (int c = 0; c < CDIM; c += 4) {
        a0 += mrow[c + 0] * wsT[(c + 0) * CDIM + o];
        a1 += mrow[c + 1] * wsT[(c + 1) * CDIM + o];
        a2 += mrow[c + 2] * wsT[(c + 2) * CDIM + o];
        a3 += mrow[c + 3] * wsT[(c + 3) * CDIM + o];
    }
    xk[(b * Lt + L + n) * CDIM + o] = (a0 + a1) + (a2 + a3);
}

// ---------------------------------------------------------------------------
// LayerNorm + exact GELU: read fp32, write bf16. One block per row.
// ---------------------------------------------------------------------------
__global__ void ln_gelu_kernel(const float* __restrict__ in,
                               __nv_bfloat16* __restrict__ outb,
                               const float* __restrict__ g,
                               const float* __restrict__ be) {
    __shared__ float sm1[4], sm2[4];
    int r = blockIdx.x;
    int t = threadIdx.x, w = t >> 5, lane = t & 31;
    float v = in[(size_t)r * CDIM + t];
    float s1 = v, s2 = v * v;
#pragma unroll
    for (int off = 16; off > 0; off >>= 1) {
        s1 += __shfl_xor_sync(0xffffffffu, s1, off);
        s2 += __shfl_xor_sync(0xffffffffu, s2, off);
    }
    if (lane == 0) { sm1[w] = s1; sm2[w] = s2; }
    __syncthreads();
    s1 = (sm1[0] + sm1[1]) + (sm1[2] + sm1[3]);
    s2 = (sm2[0] + sm2[1]) + (sm2[2] + sm2[3]);
    float mu  = s1 * (1.f / 128.f);
    float var = fmaxf(s2 * (1.f / 128.f) - mu * mu, 0.f);
    float y = (v - mu) * rsqrtf(var + 1e-5f) * g[t] + be[t];
    float gel = 0.5f * y * (1.f + erff(y * 0.70710678118654752f));
    outb[(size_t)r * CDIM + t] = __float2bfloat16(gel);
}

// ---------------------------------------------------------------------------
// v_mod: spatial tokens get v + depthwise3x3(v) + bias; msg tokens get 2v.
// ---------------------------------------------------------------------------
__global__ void vmod_kernel(const float* __restrict__ kv,
                            const float* __restrict__ lw,
                            const float* __restrict__ lb,
                            float* __restrict__ vm,
                            int Hr, int Wr, int L, int Lt) {
    int ch = threadIdx.x;  // 0..63
    int r  = blockIdx.x;   // B*Lt
    int b = r / Lt, l = r - b * Lt;
    float self = kv[((size_t)b * Lt + l) * CDIM + 64 + ch];
    float o;
    if (l < L) {
        int hr = l / Wr, wr = l - hr * Wr;
        float acc = lb[ch];
#pragma unroll
        for (int dy = 0; dy < 3; dy++) {
#pragma unroll
            for (int dx = 0; dx < 3; dx++) {
                int yy = hr + dy - 1, xx = wr + dx - 1;
                if (yy >= 0 && yy < Hr && xx >= 0 && xx < Wr)
                    acc += lw[ch * 9 + dy * 3 + dx] *
                           kv[((size_t)b * Lt + yy * Wr + xx) * CDIM + 64 + ch];
            }
        }
        o = self + acc;
    } else {
        o = 2.f * self;
    }
    vm[((size_t)b * Lt + l) * 64 + ch] = o;
}

// ---------------------------------------------------------------------------
// bf16 tensor-core flash attention (mma.sync.m16n8k16, fp32 accumulate).
// Block = (qtile of 64, hg in 0..3, batch). 4 warps, each owns 16 query rows.
// Q is pre-scaled bf16; output written bf16 for the PROJ GEMM.
// ---------------------------------------------------------------------------
__global__ void attn_mma_kernel(const __nv_bfloat16* __restrict__ qb,
                                const float* __restrict__ kv1,
                                const float* __restrict__ vm1,
                                const float* __restrict__ kv2,
                                const float* __restrict__ vm2,
                                __nv_bfloat16* __restrict__ outb) {
    __shared__ __nv_bfloat16 Qs[64][40];
    __shared__ __nv_bfloat16 Ks[64][40];
    __shared__ __nv_bfloat16 Vt[32][72];   // V transposed [d][key]

    const int tid  = threadIdx.x;
    const int warp = tid >> 5;
    const int lane = tid & 31;
    const int qt = blockIdx.x, hg = blockIdx.y, b = blockIdx.z;
    const int br = hg >> 1, hh = hg & 1;
    const float* kvp = br ? kv2 : kv1;
    const float* vmp = br ? vm2 : vm1;
    const int Lt = br ? LT2 : LT1;
    const int n0 = qt * 64;

    // load Q tile (already scaled, bf16)
#pragma unroll
    for (int i = 0; i < 16; i++) {
        int idx = tid + i * 128;
        int r = idx >> 5, d = idx & 31;
        int n = n0 + r;
        Qs[r][d] = (n < NTOT) ? qb[((size_t)b * NTOT + n) * CDIM + hg * DH + d]
                              : __float2bfloat16(0.f);
    }
    __syncthreads();

    const int r0 = warp * 16 + (lane >> 2);
    const int m2 = (lane & 3) * 2;

    uint32_t qa[2][4];
#pragma unroll
    for (int kt = 0; kt < 2; kt++) {
        qa[kt][0] = *(const uint32_t*)&Qs[r0][kt * 16 + m2];
        qa[kt][1] = *(const uint32_t*)&Qs[r0 + 8][kt * 16 + m2];
        qa[kt][2] = *(const uint32_t*)&Qs[r0][kt * 16 + m2 + 8];
        qa[kt][3] = *(const uint32_t*)&Qs[r0 + 8][kt * 16 + m2 + 8];
    }

    float o[4][4];
#pragma unroll
    for (int i = 0; i < 4; i++)
#pragma unroll
        for (int j = 0; j < 4; j++) o[i][j] = 0.f;
    float m0 = -1e30f, m1 = -1e30f, l0 = 0.f, l1 = 0.f;

    const int nc = (Lt + 63) >> 6;
    for (int ci = 0; ci < nc; ci++) {
        const int c0 = ci << 6;
        __syncthreads();
#pragma unroll
        for (int i = 0; i < 16; i++) {
            int idx = tid + i * 128;
            int r = idx >> 5, d = idx & 31;
            int gl = c0 + r;
            float kk = 0.f, vv = 0.f;
            if (gl < Lt) {
                kk = kvp[((size_t)b * Lt + gl) * CDIM + hh * DH + d];
                vv = vmp[((size_t)b * Lt + gl) * 64 + hh * DH + d];
            }
            Ks[r][d] = __float2bfloat16(kk);
            Vt[d][r] = __float2bfloat16(vv);
        }
        __syncthreads();

        float s[8][4];
#pragma unroll
        for (int nt = 0; nt < 8; nt++) { s[nt][0] = s[nt][1] = s[nt][2] = s[nt][3] = 0.f; }
#pragma unroll
        for (int nt = 0; nt < 8; nt++) {
#pragma unroll
            for (int kt = 0; kt < 2; kt++) {
                uint32_t b0 = *(const uint32_t*)&Ks[nt * 8 + (lane >> 2)][kt * 16 + m2];
                uint32_t b1 = *(const uint32_t*)&Ks[nt * 8 + (lane >> 2)][kt * 16 + m2 + 8];
                mma_bf16(s[nt], qa[kt][0], qa[kt][1], qa[kt][2], qa[kt][3], b0, b1);
            }
        }

        float mx0 = m0, mx1 = m1;
#pragma unroll
        for (int nt = 0; nt < 8; nt++) {
            int gc = c0 + nt * 8 + m2;
            if (gc >= Lt)     { s[nt][0] = -1e30f; s[nt][2] = -1e30f; }
            if (gc + 1 >= Lt) { s[nt][1] = -1e30f; s[nt][3] = -1e30f; }
            mx0 = fmaxf(mx0, fmaxf(s[nt][0], s[nt][1]));
            mx1 = fmaxf(mx1, fmaxf(s[nt][2], s[nt][3]));
        }
        mx0 = fmaxf(mx0, __shfl_xor_sync(0xffffffffu, mx0, 1));
        mx0 = fmaxf(mx0, __shfl_xor_sync(0xffffffffu, mx0, 2));
        mx1 = fmaxf(mx1, __shfl_xor_sync(0xffffffffu, mx1, 1));
        mx1 = fmaxf(mx1, __shfl_xor_sync(0xffffffffu, mx1, 2));
        float corr0 = __expf(m0 - mx0), corr1 = __expf(m1 - mx1);
        m0 = mx0; m1 = mx1;

        float ls0 = 0.f, ls1 = 0.f;
#pragma unroll
        for (int nt = 0; nt < 8; nt++) {
            s[nt][0] = __expf(s[nt][0] - m0);
            s[nt][1] = __expf(s[nt][1] - m0);
            s[nt][2] = __expf(s[nt][2] - m1);
            s[nt][3] = __expf(s[nt][3] - m1);
            ls0 += s[nt][0] + s[nt][1];
            ls1 += s[nt][2] + s[nt][3];
        }
        ls0 += __shfl_xor_sync(0xffffffffu, ls0, 1);
        ls0 += __shfl_xor_sync(0xffffffffu, ls0, 2);
        ls1 += __shfl_xor_sync(0xffffffffu, ls1, 1);
        ls1 += __shfl_xor_sync(0xffffffffu, ls1, 2);
        l0 = l0 * corr0 + ls0;
        l1 = l1 * corr1 + ls1;
#pragma unroll
        for (int nt = 0; nt < 4; nt++) {
            o[nt][0] *= corr0; o[nt][1] *= corr0;
            o[nt][2] *= corr1; o[nt][3] *= corr1;
        }

#pragma unroll
        for (int kt = 0; kt < 4; kt++) {
            uint32_t a0 = pack_bf16x2(s[2 * kt][0],     s[2 * kt][1]);
            uint32_t a1 = pack_bf16x2(s[2 * kt][2],     s[2 * kt][3]);
            uint32_t a2 = pack_bf16x2(s[2 * kt + 1][0], s[2 * kt + 1][1]);
            uint32_t a3 = pack_bf16x2(s[2 * kt + 1][2], s[2 * kt + 1][3]);
#pragma unroll
            for (int nt = 0; nt < 4; nt++) {
                uint32_t b0 = *(const uint32_t*)&Vt[nt * 8 + (lane >> 2)][kt * 16 + m2];
                uint32_t b1 = *(const uint32_t*)&Vt[nt * 8 + (lane >> 2)][kt * 16 + m2 + 8];
                mma_bf16(o[nt], a0, a1, a2, a3, b0, b1);
            }
        }
    }

    float inv0 = 1.f / l0, inv1 = 1.f / l1;
    int nr0 = n0 + r0, nr1 = nr0 + 8;
#pragma unroll
    for (int nt = 0; nt < 4; nt++) {
        int col = hg * DH + nt * 8 + m2;
        if (nr0 < NTOT)
            *(uint32_t*)&outb[((size_t)b * NTOT + nr0) * CDIM + col] =
                pack_bf16x2(o[nt][0] * inv0, o[nt][1] * inv0);
        if (nr1 < NTOT)
            *(uint32_t*)&outb[((size_t)b * NTOT + nr1) * CDIM + col] =
                pack_bf16x2(o[nt][2] * inv1, o[nt][3] * inv1);
    }
}

// ---------------------------------------------------------------------------
extern "C" void kernel_launch(void* const* d_in, const int* in_sizes, int n_in,
                              void* d_out, int out_size) {
    const float* x     = (const float*)d_in[0];
    const float* msg   = (const float*)d_in[1];
    const float* Wq    = (const float*)d_in[2];
    const float* bq    = (const float*)d_in[3];
    const float* sr1w  = (const float*)d_in[4];
    const float* sr1b  = (const float*)d_in[5];
    const float* ln1g  = (const float*)d_in[6];
    const float* ln1b  = (const float*)d_in[7];
    const float* sr2w  = (const float*)d_in[8];
    const float* sr2b  = (const float*)d_in[9];
    const float* ln2g  = (const float*)d_in[10];
    const float* ln2b  = (const float*)d_in[11];
    const float* kv1w  = (const float*)d_in[12];
    const float* kv1b  = (const float*)d_in[13];
    const float* kv2w  = (const float*)d_in[14];
    const float* kv2b  = (const float*)d_in[15];
    const float* lc1w  = (const float*)d_in[16];
    const float* lc1b  = (const float*)d_in[17];
    const float* lc2w  = (const float*)d_in[18];
    const float* lc2b  = (const float*)d_in[19];
    const float* projw = (const float*)d_in[20];
    const float* projb = (const float*)d_in[21];
    (void)in_sizes; (void)n_in; (void)out_size;

    float* out_img = (float*)d_out;
    float* out_msg = out_img + (size_t)BSZ * N0 * CDIM;

    float *xk1, *xk2, *kv1, *kv2, *v1m, *v2m, *ws1, *ws2;
    __nv_bfloat16 *xb, *msgb, *qb, *xk1b, *xk2b, *x12b;
    __nv_bfloat16 *wqb, *sr1wb, *sr2wb, *kv1wb, *kv2wb, *projwb;
    cudaGetSymbolAddress((void**)&xk1,   g_xk1);
    cudaGetSymbolAddress((void**)&xk2,   g_xk2);
    cudaGetSymbolAddress((void**)&kv1,   g_kv1);
    cudaGetSymbolAddress((void**)&kv2,   g_kv2);
    cudaGetSymbolAddress((void**)&v1m,   g_v1m);
    cudaGetSymbolAddress((void**)&v2m,   g_v2m);
    cudaGetSymbolAddress((void**)&ws1,   g_ws1);
    cudaGetSymbolAddress((void**)&ws2,   g_ws2);
    cudaGetSymbolAddress((void**)&xb,    g_xb);
    cudaGetSymbolAddress((void**)&msgb,  g_msgb);
    cudaGetSymbolAddress((void**)&qb,    g_qb);
    cudaGetSymbolAddress((void**)&xk1b,  g_xk1b);
    cudaGetSymbolAddress((void**)&xk2b,  g_xk2b);
    cudaGetSymbolAddress((void**)&x12b,  g_x12b);
    cudaGetSymbolAddress((void**)&wqb,   g_wqb);
    cudaGetSymbolAddress((void**)&sr1wb, g_sr1wb);
    cudaGetSymbolAddress((void**)&sr2wb, g_sr2wb);
    cudaGetSymbolAddress((void**)&kv1wb, g_kv1wb);
    cudaGetSymbolAddress((void**)&kv2wb, g_kv2wb);
    cudaGetSymbolAddress((void**)&projwb, g_projwb);

    // 0. conversions / weight prep
    f2b_kernel<<<(BSZ * N0 * CDIM + 255) / 256, 256>>>(x, xb, BSZ * N0 * CDIM);
    f2b_kernel<<<(BSZ * NMSG * CDIM + 255) / 256, 256>>>(msg, msgb, BSZ * NMSG * CDIM);
    f2b_kernel<<<(CDIM * CDIM + 255) / 256, 256>>>(Wq, wqb, CDIM * CDIM);
    f2b_kernel<<<(CDIM * CDIM + 255) / 256, 256>>>(kv1w, kv1wb, CDIM * CDIM);
    f2b_kernel<<<(CDIM * CDIM + 255) / 256, 256>>>(kv2w, kv2wb, CDIM * CDIM);
    f2b_kernel<<<(CDIM * CDIM + 255) / 256, 256>>>(projw, projwb, CDIM * CDIM);
    wreorder_kernel<<<(CDIM * CDIM * 16 + 255) / 256, 256>>>(sr1w, sr1wb, 16);
    wreorder_kernel<<<(CDIM * CDIM * 4 + 255) / 256, 256>>>(sr2w, sr2wb, 4);
    wsum_kernel<<<(CDIM * CDIM + 255) / 256, 256>>>(sr1w, ws1, 16);
    wsum_kernel<<<(CDIM * CDIM + 255) / 256, 256>>>(sr2w, ws2, 4);

    // 1. Q projection -> bf16 (scale folded in)
    bgemm_kernel<MODE_Q, 1><<<(BSZ * NTOT + 63) / 64, 256>>>(
        nullptr, xb, msgb, wqb, bq, nullptr, nullptr, qb, nullptr, nullptr,
        BSZ * NTOT, CDIM, 0, 0, 0);

    // 2. SR patch-embed convs (K reordered: pos*128+c)
    bgemm_kernel<MODE_PATCH, 4><<<(BSZ * L1 + 63) / 64, 256>>>(
        nullptr, xb, nullptr, sr1wb, sr1b, xk1, nullptr, nullptr, nullptr, nullptr,
        BSZ * L1, CDIM * 16, WR1, L1, LT1);
    bgemm_kernel<MODE_PATCH, 2><<<(BSZ * L2 + 63) / 64, 256>>>(
        nullptr, xb, nullptr, sr2wb, sr2b, xk2, nullptr, nullptr, nullptr, nullptr,
        BSZ * L2, CDIM * 4, WR2, L2, LT2);

    // 3. msg tokens through summed SR weights (fp32)
    msgr2_kernel<<<BSZ * NMSG, 128>>>(msg, ws1, sr1b, xk1, L1, LT1);
    msgr2_kernel<<<BSZ * NMSG, 128>>>(msg, ws2, sr2b, xk2, L2, LT2);

    // 4. LayerNorm + GELU -> bf16
    ln_gelu_kernel<<<BSZ * LT1, 128>>>(xk1, xk1b, ln1g, ln1b);
    ln_gelu_kernel<<<BSZ * LT2, 128>>>(xk2, xk2b, ln2g, ln2b);

    // 5. KV projections (bf16 in, fp32 out for vmod/attention-K)
    bgemm_kernel<MODE_PLAIN, 1><<<(BSZ * LT1 + 63) / 64, 256>>>(
        xk1b, nullptr, nullptr, kv1wb, kv1b, kv1, nullptr, nullptr, nullptr, nullptr,
        BSZ * LT1, CDIM, 0, 0, 0);
    bgemm_kernel<MODE_PLAIN, 1><<<(BSZ * LT2 + 63) / 64, 256>>>(
        xk2b, nullptr, nullptr, kv2wb, kv2b, kv2, nullptr, nullptr, nullptr, nullptr,
        BSZ * LT2, CDIM, 0, 0, 0);

    // 6. V augmentation
    vmod_kernel<<<BSZ * LT1, 64>>>(kv1, lc1w, lc1b, v1m, HR1, WR1, L1, LT1);
    vmod_kernel<<<BSZ * LT2, 64>>>(kv2, lc2w, lc2b, v2m, HR2, WR2, L2, LT2);

    // 7. attention (both branches/heads), bf16 out
    {
        dim3 grid((NTOT + 63) / 64, 4, BSZ);
        attn_mma_kernel<<<grid, 128>>>(qb, kv1, v1m, kv2, v2m, x12b);
    }

    // 8. output projection + residual, split write to d_out
    bgemm_kernel<MODE_PROJ, 1><<<(BSZ * NTOT + 63) / 64, 256>>>(
        x12b, nullptr, nullptr, projwb, projb, out_img, out_msg, nullptr, x, msg,
        BSZ * NTOT, CDIM, 0, 0, 0);
}

// round 9
// speedup vs baseline: 6.4451x; 1.5888x over previous
#include <cuda_runtime.h>
#include <cuda_bf16.h>
#include <stdint.h>
#include <math.h>

#define BSZ   8
#define N0    4096
#define NMSG  4
#define NTOT  4100
#define CDIM  128
#define DH    32
#define ATT_SCALE 0.17677669529663687f  // 1/sqrt(32)

#define L1   256
#define LT1  260
#define HR1  16
#define WR1  16
#define L2   1024
#define LT2  1028
#define HR2  32
#define WR2  32

#define M_Q   (BSZ * NTOT)   // 32800
#define M_P1  (BSZ * L1)     // 2048
#define M_P2  (BSZ * L2)     // 8192
#define M_KV1 (BSZ * LT1)    // 2080
#define M_KV2 (BSZ * LT2)    // 8224

// stage1 grid layout
#define NQ_TILES  ((M_Q + 63) / 64)            // 513
#define P1_TILES  (M_P1 / 64)                  // 32
#define KSPLIT1   4
#define P1_BLKS   (P1_TILES * KSPLIT1)         // 128
#define P2_TILES  (M_P2 / 64)                  // 128
#define STAGE1_GRID (NQ_TILES + P1_BLKS + P2_TILES)

// kv grid
#define KV1_TILES ((M_KV1 + 63) / 64)          // 33
#define KV2_TILES ((M_KV2 + 63) / 64)          // 129

// ---------------- scratch (static device globals; no allocs) ----------------
__device__ float g_p1[KSPLIT1 * M_P1 * CDIM];  // PATCH1 K-split partials (no bias)
__device__ float g_p2[M_P2 * CDIM];            // PATCH2 output (no bias)
__device__ float g_v1f[M_KV1 * 64];            // V fp32 (pre-dwconv)
__device__ float g_v2f[M_KV2 * 64];
__device__ float g_ws1[CDIM * CDIM];           // transposed summed SR weights [c][o]
__device__ float g_ws2[CDIM * CDIM];

__device__ __nv_bfloat16 g_xb[BSZ * N0 * CDIM];
__device__ __nv_bfloat16 g_msgb[BSZ * NMSG * CDIM];
__device__ __nv_bfloat16 g_qb[M_Q * CDIM];     // Q (pre-scaled)
__device__ __nv_bfloat16 g_xk1b[M_KV1 * CDIM]; // post LN+GELU
__device__ __nv_bfloat16 g_xk2b[M_KV2 * CDIM];
__device__ __nv_bfloat16 g_k1b[M_KV1 * 64];    // K bf16
__device__ __nv_bfloat16 g_k2b[M_KV2 * 64];
__device__ __nv_bfloat16 g_v1mb[M_KV1 * 64];   // V + dwconv, bf16
__device__ __nv_bfloat16 g_v2mb[M_KV2 * 64];
__device__ __nv_bfloat16 g_x12b[M_Q * CDIM];   // attention outputs

__device__ __nv_bfloat16 g_wqb[CDIM * CDIM];
__device__ __nv_bfloat16 g_sr1wb[CDIM * CDIM * 16]; // [o][pos*128+c]
__device__ __nv_bfloat16 g_sr2wb[CDIM * CDIM * 4];
__device__ __nv_bfloat16 g_kv1wb[CDIM * CDIM];
__device__ __nv_bfloat16 g_kv2wb[CDIM * CDIM];
__device__ __nv_bfloat16 g_projwb[CDIM * CDIM];

// ---------------------------------------------------------------------------
__device__ __forceinline__ void mma_bf16(float c[4],
                                         uint32_t a0, uint32_t a1, uint32_t a2, uint32_t a3,
                                         uint32_t b0, uint32_t b1) {
    asm volatile(
        "mma.sync.aligned.m16n8k16.row.col.f32.bf16.bf16.f32 "
        "{%0,%1,%2,%3}, {%4,%5,%6,%7}, {%8,%9}, {%0,%1,%2,%3};"
        : "+f"(c[0]), "+f"(c[1]), "+f"(c[2]), "+f"(c[3])
        : "r"(a0), "r"(a1), "r"(a2), "r"(a3), "r"(b0), "r"(b1));
}

__device__ __forceinline__ uint32_t pack_bf16x2(float lo, float hi) {
    __nv_bfloat162 h = __floats2bfloat162_rn(lo, hi);
    return *reinterpret_cast<uint32_t*>(&h);
}

// ---------------------------------------------------------------------------
// prep: all fp32->bf16 conversions, SR weight reorder, summed-SR weights.
// Segments keyed by blockIdx.x range; 256 threads.
// ---------------------------------------------------------------------------
#define PS0 4096                  // xb (float4 per thread)
#define PS1 (PS0 + 16)            // msgb
#define PS2 (PS1 + 64)            // wqb
#define PS3 (PS2 + 64)            // kv1wb
#define PS4 (PS3 + 64)            // kv2wb
#define PS5 (PS4 + 64)            // projwb
#define PS6 (PS5 + 1024)          // wreorder sr1
#define PS7 (PS6 + 256)           // wreorder sr2
#define PS8 (PS7 + 64)            // wsum1
#define PS9 (PS8 + 64)            // wsum2   -> grid = PS9

__global__ void prep_kernel(const float* __restrict__ x,   const float* __restrict__ msg,
                            const float* __restrict__ Wq,  const float* __restrict__ kv1w,
                            const float* __restrict__ kv2w, const float* __restrict__ projw,
                            const float* __restrict__ sr1w, const float* __restrict__ sr2w) {
    int bid = blockIdx.x, t = threadIdx.x;
    if (bid < PS0) {
        int i = (bid * 256 + t) * 4;
        float4 v = *(const float4*)(x + i);
        __nv_bfloat16* o = g_xb + i;
        o[0] = __float2bfloat16(v.x); o[1] = __float2bfloat16(v.y);
        o[2] = __float2bfloat16(v.z); o[3] = __float2bfloat16(v.w);
    } else if (bid < PS1) {
        int i = (bid - PS0) * 256 + t;
        g_msgb[i] = __float2bfloat16(msg[i]);
    } else if (bid < PS2) {
        int i = (bid - PS1) * 256 + t;  g_wqb[i]   = __float2bfloat16(Wq[i]);
    } else if (bid < PS3) {
        int i = (bid - PS2) * 256 + t;  g_kv1wb[i] = __float2bfloat16(kv1w[i]);
    } else if (bid < PS4) {
        int i = (bid - PS3) * 256 + t;  g_kv2wb[i] = __float2bfloat16(kv2w[i]);
    } else if (bid < PS5) {
        int i = (bid - PS4) * 256 + t;  g_projwb[i] = __float2bfloat16(projw[i]);
    } else if (bid < PS6) {
        int idx = (bid - PS5) * 256 + t;          // [o][c][pos] src
        int o = idx >> 11;                         // / (128*16)
        int rem = idx & 2047;
        int cch = rem >> 4, pos = rem & 15;
        g_sr1wb[(size_t)o * 2048 + pos * CDIM + cch] = __float2bfloat16(sr1w[idx]);
    } else if (bid < PS7) {
        int idx = (bid - PS6) * 256 + t;
        int o = idx >> 9;                          // / (128*4)
        int rem = idx & 511;
        int cch = rem >> 2, pos = rem & 3;
        g_sr2wb[(size_t)o * 512 + pos * CDIM + cch] = __float2bfloat16(sr2w[idx]);
    } else if (bid < PS8) {
        int idx = (bid - PS7) * 256 + t;
        int c = idx >> 7, o = idx & 127;
        const float* p = sr1w + (o * CDIM + c) * 16;
        float s = 0.f;
#pragma unroll
        for (int i = 0; i < 16; i++) s += p[i];
        g_ws1[c * CDIM + o] = s;
    } else {
        int idx = (bid - PS8) * 256 + t;
        int c = idx >> 7, o = idx & 127;
        const float* p = sr2w + (o * CDIM + c) * 4;
        float s = 0.f;
#pragma unroll
        for (int i = 0; i < 4; i++) s += p[i];
        g_ws2[c * CDIM + o] = s;
    }
}

// ---------------------------------------------------------------------------
// stage1: Q projection + both SR patch-embed GEMMs in ONE launch.
// Tile 64 rows x 128 cols, 256 threads / 8 warps, m16n8k16 bf16.
// bid < NQ_TILES: Q mode. Next P1_BLKS: PATCH1 (K split x4, partial out, no bias).
// Next P2_TILES: PATCH2 (full K=512, no bias).
// ---------------------------------------------------------------------------
__global__ void stage1_kernel(const float* __restrict__ bq) {
    __shared__ __nv_bfloat16 Xs[64][40];
    __shared__ __nv_bfloat16 Wsm[128][40];

    const int tid  = threadIdx.x;
    const int warp = tid >> 5;
    const int lane = tid & 31;
    const int mrow = (warp & 3) * 16;
    const int colBase = (warp >> 2) * 64;
    const int bid = blockIdx.x;

    int mode, S = 4, rowBase, K, kbase = 0, KTOT, M, Lloc = L1;
    const __nv_bfloat16* Wb;
    float* outP = nullptr;
    if (bid < NQ_TILES) {
        mode = 0; rowBase = bid * 64; K = 128; KTOT = 128; M = M_Q; Wb = g_wqb;
    } else if (bid < NQ_TILES + P1_BLKS) {
        int q = bid - NQ_TILES;
        mode = 1; S = 4; Lloc = L1;
        rowBase = (q >> 2) * 64;
        int kseg = q & 3;
        K = 512; kbase = kseg * 512; KTOT = 2048; M = M_P1;
        Wb = g_sr1wb; outP = g_p1 + (size_t)kseg * M_P1 * CDIM;
    } else {
        int q = bid - NQ_TILES - P1_BLKS;
        mode = 1; S = 2; Lloc = L2;
        rowBase = q * 64;
        K = 512; kbase = 0; KTOT = 512; M = M_P2;
        Wb = g_sr2wb; outP = g_p2;
    }

    const int lrow = tid >> 2;
    const int koff = (tid & 3) * 8;
    const int gr = rowBase + lrow;
    const bool valid = gr < M;

    const __nv_bfloat16* srcRow = nullptr;
    int pb = 0, phr = 0, pwr = 0;
    if (mode == 0) {
        if (valid) {
            int b = gr / NTOT, n = gr - b * NTOT;
            srcRow = (n < N0) ? g_xb + ((size_t)b * N0 + n) * CDIM
                              : g_msgb + ((size_t)b * NMSG + (n - N0)) * CDIM;
        }
    } else {
        if (valid) {
            pb = gr / Lloc; int l = gr - pb * Lloc;
            int Wr = (S == 4) ? WR1 : WR2;
            phr = l / Wr; pwr = l - phr * Wr;
        }
    }

    const int fr = lane >> 2;
    const int m2 = (lane & 3) * 2;

    float c[8][4];
#pragma unroll
    for (int nt = 0; nt < 8; nt++) { c[nt][0] = c[nt][1] = c[nt][2] = c[nt][3] = 0.f; }

    for (int k0 = 0; k0 < K; k0 += 32) {
        uint4 xv = make_uint4(0u, 0u, 0u, 0u);
        if (valid) {
            if (mode == 1) {
                int gk = kbase + k0;
                int pos = gk >> 7;
                int ky = (S == 4) ? (pos >> 2) : (pos >> 1);
                int kx = (S == 4) ? (pos & 3)  : (pos & 1);
                int p = (phr * S + ky) * 64 + pwr * S + kx;
                xv = *(const uint4*)(g_xb + ((size_t)pb * N0 + p) * CDIM + (gk & 127) + koff);
            } else {
                xv = *(const uint4*)(srcRow + k0 + koff);
            }
        }
        *(uint4*)&Xs[lrow][koff] = xv;
        {
            const __nv_bfloat16* wp = Wb + (size_t)(tid >> 1) * KTOT + kbase + k0 + (tid & 1) * 16;
            *(uint4*)&Wsm[tid >> 1][(tid & 1) * 16]     = *(const uint4*)wp;
            *(uint4*)&Wsm[tid >> 1][(tid & 1) * 16 + 8] = *(const uint4*)(wp + 8);
        }
        __syncthreads();

#pragma unroll
        for (int kt = 0; kt < 2; kt++) {
            uint32_t a0 = *(const uint32_t*)&Xs[mrow + fr][kt * 16 + m2];
            uint32_t a1 = *(const uint32_t*)&Xs[mrow + fr + 8][kt * 16 + m2];
            uint32_t a2 = *(const uint32_t*)&Xs[mrow + fr][kt * 16 + m2 + 8];
            uint32_t a3 = *(const uint32_t*)&Xs[mrow + fr + 8][kt * 16 + m2 + 8];
#pragma unroll
            for (int nt = 0; nt < 8; nt++) {
                uint32_t b0 = *(const uint32_t*)&Wsm[colBase + nt * 8 + fr][kt * 16 + m2];
                uint32_t b1 = *(const uint32_t*)&Wsm[colBase + nt * 8 + fr][kt * 16 + m2 + 8];
                mma_bf16(c[nt], a0, a1, a2, a3, b0, b1);
            }
        }
        __syncthreads();
    }

    const int r0 = rowBase + mrow + fr;
    const int r1 = r0 + 8;
#pragma unroll
    for (int nt = 0; nt < 8; nt++) {
        int col = colBase + nt * 8 + m2;
        if (mode == 0) {
            float bb0 = bq[col], bb1 = bq[col + 1];
            if (r0 < M) *(uint32_t*)&g_qb[(size_t)r0 * CDIM + col] =
                pack_bf16x2((c[nt][0] + bb0) * ATT_SCALE, (c[nt][1] + bb1) * ATT_SCALE);
            if (r1 < M) *(uint32_t*)&g_qb[(size_t)r1 * CDIM + col] =
                pack_bf16x2((c[nt][2] + bb0) * ATT_SCALE, (c[nt][3] + bb1) * ATT_SCALE);
        } else {
            if (r0 < M) *(float2*)&outP[(size_t)r0 * CDIM + col] = make_float2(c[nt][0], c[nt][1]);
            if (r1 < M) *(float2*)&outP[(size_t)r1 * CDIM + col] = make_float2(c[nt][2], c[nt][3]);
        }
    }
}

// ---------------------------------------------------------------------------
// LN+GELU fused: sums PATCH partials (+SR bias), computes msg-token SR matvec
// for rows >= L, LayerNorm + exact GELU, writes bf16. One 128-thr block / row.
// grid = M_KV1 + M_KV2.
// ---------------------------------------------------------------------------
__global__ void lnfuse_kernel(const float* __restrict__ msg,
                              const float* __restrict__ sr1b, const float* __restrict__ sr2b,
                              const float* __restrict__ ln1g, const float* __restrict__ ln1b,
                              const float* __restrict__ ln2g, const float* __restrict__ ln2b) {
    __shared__ float sm1[4], sm2[4];
    __shared__ float mrow[CDIM];
    int bid = blockIdx.x;
    int t = threadIdx.x, w = t >> 5, lane = t & 31;

    int br, b, l;
    if (bid < M_KV1) { br = 0; b = bid / LT1; l = bid - b * LT1; }
    else { int r2 = bid - M_KV1; br = 1; b = r2 / LT2; l = r2 - b * LT2; }

    const int Lloc = br ? L2 : L1;
    float v;
    if (l < Lloc) {
        if (br == 0) {
            size_t o = ((size_t)b * L1 + l) * CDIM + t;
            v = g_p1[o] + g_p1[(size_t)M_P1 * CDIM + o] + g_p1[(size_t)2 * M_P1 * CDIM + o]
              + g_p1[(size_t)3 * M_P1 * CDIM + o] + sr1b[t];
        } else {
            v = g_p2[((size_t)b * L2 + l) * CDIM + t] + sr2b[t];
        }
    } else {
        // msg token through summed SR weights
        int n = l - Lloc;
        mrow[t] = msg[((size_t)b * NMSG + n) * CDIM + t];
        __syncthreads();
        const float* wsT = br ? g_ws2 : g_ws1;
        float a0 = 0.f, a1 = 0.f, a2 = 0.f, a3 = 0.f;
#pragma unroll 8
        for (int cc = 0; cc < CDIM; cc += 4) {
            a0 += mrow[cc + 0] * wsT[(cc + 0) * CDIM + t];
            a1 += mrow[cc + 1] * wsT[(cc + 1) * CDIM + t];
            a2 += mrow[cc + 2] * wsT[(cc + 2) * CDIM + t];
            a3 += mrow[cc + 3] * wsT[(cc + 3) * CDIM + t];
        }
        v = (a0 + a1) + (a2 + a3) + (br ? sr2b[t] : sr1b[t]);
    }
    __syncthreads();

    float s1 = v, s2 = v * v;
#pragma unroll
    for (int off = 16; off > 0; off >>= 1) {
        s1 += __shfl_xor_sync(0xffffffffu, s1, off);
        s2 += __shfl_xor_sync(0xffffffffu, s2, off);
    }
    if (lane == 0) { sm1[w] = s1; sm2[w] = s2; }
    __syncthreads();
    s1 = (sm1[0] + sm1[1]) + (sm1[2] + sm1[3]);
    s2 = (sm2[0] + sm2[1]) + (sm2[2] + sm2[3]);
    float mu  = s1 * (1.f / 128.f);
    float var = fmaxf(s2 * (1.f / 128.f) - mu * mu, 0.f);
    const float* g  = br ? ln2g : ln1g;
    const float* be = br ? ln2b : ln1b;
    float y = (v - mu) * rsqrtf(var + 1e-5f) * g[t] + be[t];
    float gel = 0.5f * y * (1.f + erff(y * 0.70710678118654752f));
    __nv_bfloat16* ob = br ? g_xk2b : g_xk1b;
    size_t row = br ? ((size_t)b * LT2 + l) : ((size_t)b * LT1 + l);
    ob[row * CDIM + t] = __float2bfloat16(gel);
}

// ---------------------------------------------------------------------------
// KV projections, both branches in one launch. K half (cols<64) -> bf16,
// V half (cols>=64) -> fp32 (for dwconv).
// ---------------------------------------------------------------------------
__global__ void kv_kernel(const float* __restrict__ kv1b_, const float* __restrict__ kv2b_) {
    __shared__ __nv_bfloat16 Xs[64][40];
    __shared__ __nv_bfloat16 Wsm[128][40];

    const int tid  = threadIdx.x;
    const int warp = tid >> 5;
    const int lane = tid & 31;
    const int mrow = (warp & 3) * 16;
    const int colBase = (warp >> 2) * 64;
    const int bid = blockIdx.x;

    int rowBase, M;
    const __nv_bfloat16 *Ab, *Wb;
    const float* bias;
    __nv_bfloat16* kb;
    float* vf;
    if (bid < KV1_TILES) {
        rowBase = bid * 64; M = M_KV1;
        Ab = g_xk1b; Wb = g_kv1wb; bias = kv1b_; kb = g_k1b; vf = g_v1f;
    } else {
        rowBase = (bid - KV1_TILES) * 64; M = M_KV2;
        Ab = g_xk2b; Wb = g_kv2wb; bias = kv2b_; kb = g_k2b; vf = g_v2f;
    }

    const int lrow = tid >> 2;
    const int koff = (tid & 3) * 8;
    const int gr = rowBase + lrow;
    const bool valid = gr < M;
    const int fr = lane >> 2;
    const int m2 = (lane & 3) * 2;

    float c[8][4];
#pragma unroll
    for (int nt = 0; nt < 8; nt++) { c[nt][0] = c[nt][1] = c[nt][2] = c[nt][3] = 0.f; }

    for (int k0 = 0; k0 < CDIM; k0 += 32) {
        uint4 xv = make_uint4(0u, 0u, 0u, 0u);
        if (valid) xv = *(const uint4*)(Ab + (size_t)gr * CDIM + k0 + koff);
        *(uint4*)&Xs[lrow][koff] = xv;
        {
            const __nv_bfloat16* wp = Wb + (size_t)(tid >> 1) * CDIM + k0 + (tid & 1) * 16;
            *(uint4*)&Wsm[tid >> 1][(tid & 1) * 16]     = *(const uint4*)wp;
            *(uint4*)&Wsm[tid >> 1][(tid & 1) * 16 + 8] = *(const uint4*)(wp + 8);
        }
        __syncthreads();
#pragma unroll
        for (int kt = 0; kt < 2; kt++) {
            uint32_t a0 = *(const uint32_t*)&Xs[mrow + fr][kt * 16 + m2];
            uint32_t a1 = *(const uint32_t*)&Xs[mrow + fr + 8][kt * 16 + m2];
            uint32_t a2 = *(const uint32_t*)&Xs[mrow + fr][kt * 16 + m2 + 8];
            uint32_t a3 = *(const uint32_t*)&Xs[mrow + fr + 8][kt * 16 + m2 + 8];
#pragma unroll
            for (int nt = 0; nt < 8; nt++) {
                uint32_t b0 = *(const uint32_t*)&Wsm[colBase + nt * 8 + fr][kt * 16 + m2];
                uint32_t b1 = *(const uint32_t*)&Wsm[colBase + nt * 8 + fr][kt * 16 + m2 + 8];
                mma_bf16(c[nt], a0, a1, a2, a3, b0, b1);
            }
        }
        __syncthreads();
    }

    const int r0 = rowBase + mrow + fr;
    const int r1 = r0 + 8;
#pragma unroll
    for (int nt = 0; nt < 8; nt++) {
        int col = colBase + nt * 8 + m2;
        float bb0 = bias[col], bb1 = bias[col + 1];
        float v00 = c[nt][0] + bb0, v01 = c[nt][1] + bb1;
        float v10 = c[nt][2] + bb0, v11 = c[nt][3] + bb1;
        if (col < 64) {  // K -> bf16
            if (r0 < M) *(uint32_t*)&kb[(size_t)r0 * 64 + col] = pack_bf16x2(v00, v01);
            if (r1 < M) *(uint32_t*)&kb[(size_t)r1 * 64 + col] = pack_bf16x2(v10, v11);
        } else {         // V -> fp32
            int vc = col - 64;
            if (r0 < M) *(float2*)&vf[(size_t)r0 * 64 + vc] = make_float2(v00, v01);
            if (r1 < M) *(float2*)&vf[(size_t)r1 * 64 + vc] = make_float2(v10, v11);
        }
    }
}

// ---------------------------------------------------------------------------
// v_mod both branches: spatial v + depthwise3x3(v) + bias; msg 2v. bf16 out.
// Block = 256 thr = 4 rows x 64 ch. grid = (M_KV1+M_KV2)/4.
// ---------------------------------------------------------------------------
__global__ void vmod_kernel(const float* __restrict__ lw1, const float* __restrict__ lb1,
                            const float* __restrict__ lw2, const float* __restrict__ lb2) {
    int tid = threadIdx.x;
    int ch = tid & 63;
    int row = blockIdx.x * 4 + (tid >> 6);
    if (row >= M_KV1 + M_KV2) return;

    int b, l, Hr, Wr, Lloc, Lt;
    const float *vf, *lw, *lb;
    __nv_bfloat16* vm;
    if (row < M_KV1) {
        b = row / LT1; l = row - b * LT1;
        Hr = HR1; Wr = WR1; Lloc = L1; Lt = LT1;
        vf = g_v1f; lw = lw1; lb = lb1; vm = g_v1mb;
    } else {
        int r2 = row - M_KV1;
        b = r2 / LT2; l = r2 - b * LT2;
        Hr = HR2; Wr = WR2; Lloc = L2; Lt = LT2;
        vf = g_v2f; lw = lw2; lb = lb2; vm = g_v2mb;
    }
    float self = vf[((size_t)b * Lt + l) * 64 + ch];
    float o;
    if (l < Lloc) {
        int hr = l / Wr, wr = l - hr * Wr;
        float acc = lb[ch];
#pragma unroll
        for (int dy = 0; dy < 3; dy++) {
#pragma unroll
            for (int dx = 0; dx < 3; dx++) {
                int yy = hr + dy - 1, xx = wr + dx - 1;
                if (yy >= 0 && yy < Hr && xx >= 0 && xx < Wr)
                    acc += lw[ch * 9 + dy * 3 + dx] *
                           vf[((size_t)b * Lt + yy * Wr + xx) * 64 + ch];
            }
        }
        o = self + acc;
    } else {
        o = 2.f * self;
    }
    vm[((size_t)b * Lt + l) * 64 + ch] = __float2bfloat16(o);
}

// ---------------------------------------------------------------------------
// bf16 flash attention: 128-query tiles, 8 warps (256 thr), K/V bf16 direct.
// Writes g_x12b (device global) directly — NO host-passed symbol pointers.
// grid = (ceil(NTOT/128), 4 heads, BSZ).
// ---------------------------------------------------------------------------
__global__ void attn_mma_kernel() {
    __shared__ __nv_bfloat16 Qs[128][40];
    __shared__ __nv_bfloat16 Ks[64][40];
    __shared__ __nv_bfloat16 Vt[32][72];   // V transposed [d][key]

    const int tid  = threadIdx.x;
    const int warp = tid >> 5;
    const int lane = tid & 31;
    const int qt = blockIdx.x, hg = blockIdx.y, b = blockIdx.z;
    const int br = hg >> 1, hh = hg & 1;
    const __nv_bfloat16* kb = br ? g_k2b : g_k1b;
    const __nv_bfloat16* vm = br ? g_v2mb : g_v1mb;
    const int Lt = br ? LT2 : LT1;
    const int n0 = qt * 128;

    // Q tile: 128 rows x 32 d, uint4 per thread, 2 passes
#pragma unroll
    for (int pass = 0; pass < 2; pass++) {
        int r = (tid >> 2) + pass * 64;
        int koff = (tid & 3) * 8;
        int n = n0 + r;
        uint4 v = make_uint4(0u, 0u, 0u, 0u);
        if (n < NTOT)
            v = *(const uint4*)(g_qb + ((size_t)b * NTOT + n) * CDIM + hg * DH + koff);
        *(uint4*)&Qs[r][koff] = v;
    }
    __syncthreads();

    const int fr = lane >> 2;
    const int m2 = (lane & 3) * 2;
    const int r0 = warp * 16 + fr;

    uint32_t qa[2][4];
#pragma unroll
    for (int kt = 0; kt < 2; kt++) {
        qa[kt][0] = *(const uint32_t*)&Qs[r0][kt * 16 + m2];
        qa[kt][1] = *(const uint32_t*)&Qs[r0 + 8][kt * 16 + m2];
        qa[kt][2] = *(const uint32_t*)&Qs[r0][kt * 16 + m2 + 8];
        qa[kt][3] = *(const uint32_t*)&Qs[r0 + 8][kt * 16 + m2 + 8];
    }

    float o[4][4];
#pragma unroll
    for (int i = 0; i < 4; i++)
#pragma unroll
        for (int j = 0; j < 4; j++) o[i][j] = 0.f;
    float m0 = -1e30f, m1 = -1e30f, l0 = 0.f, l1 = 0.f;

    const int nc = (Lt + 63) >> 6;
    for (int ci = 0; ci < nc; ci++) {
        const int c0 = ci << 6;
        __syncthreads();
        {   // K/V chunk: 64 keys x 32 d each; uint4 (8 bf16) per thread
            int r = tid >> 2;
            int koff = (tid & 3) * 8;
            int gl = c0 + r;
            uint4 kv4 = make_uint4(0u, 0u, 0u, 0u);
            uint4 vv4 = make_uint4(0u, 0u, 0u, 0u);
            if (gl < Lt) {
                size_t base = ((size_t)b * Lt + gl) * 64 + hh * DH + koff;
                kv4 = *(const uint4*)(kb + base);
                vv4 = *(const uint4*)(vm + base);
            }
            *(uint4*)&Ks[r][koff] = kv4;
            const __nv_bfloat16* vb = (const __nv_bfloat16*)&vv4;
#pragma unroll
            for (int j = 0; j < 8; j++) Vt[koff + j][r] = vb[j];
        }
        __syncthreads();

        float s[8][4];
#pragma unroll
        for (int nt = 0; nt < 8; nt++) { s[nt][0] = s[nt][1] = s[nt][2] = s[nt][3] = 0.f; }
#pragma unroll
        for (int nt = 0; nt < 8; nt++) {
#pragma unroll
            for (int kt = 0; kt < 2; kt++) {
                uint32_t b0 = *(const uint32_t*)&Ks[nt * 8 + fr][kt * 16 + m2];
                uint32_t b1 = *(const uint32_t*)&Ks[nt * 8 + fr][kt * 16 + m2 + 8];
                mma_bf16(s[nt], qa[kt][0], qa[kt][1], qa[kt][2], qa[kt][3], b0, b1);
            }
        }

        float mx0 = m0, mx1 = m1;
#pragma unroll
        for (int nt = 0; nt < 8; nt++) {
            int gc = c0 + nt * 8 + m2;
            if (gc >= Lt)     { s[nt][0] = -1e30f; s[nt][2] = -1e30f; }
            if (gc + 1 >= Lt) { s[nt][1] = -1e30f; s[nt][3] = -1e30f; }
            mx0 = fmaxf(mx0, fmaxf(s[nt][0], s[nt][1]));
            mx1 = fmaxf(mx1, fmaxf(s[nt][2], s[nt][3]));
        }
        mx0 = fmaxf(mx0, __shfl_xor_sync(0xffffffffu, mx0, 1));
        mx0 = fmaxf(mx0, __shfl_xor_sync(0xffffffffu, mx0, 2));
        mx1 = fmaxf(mx1, __shfl_xor_sync(0xffffffffu, mx1, 1));
        mx1 = fmaxf(mx1, __shfl_xor_sync(0xffffffffu, mx1, 2));
        float corr0 = __expf(m0 - mx0), corr1 = __expf(m1 - mx1);
        m0 = mx0; m1 = mx1;

        float ls0 = 0.f, ls1 = 0.f;
#pragma unroll
        for (int nt = 0; nt < 8; nt++) {
            s[nt][0] = __expf(s[nt][0] - m0);
            s[nt][1] = __expf(s[nt][1] - m0);
            s[nt][2] = __expf(s[nt][2] - m1);
            s[nt][3] = __expf(s[nt][3] - m1);
            ls0 += s[nt][0] + s[nt][1];
            ls1 += s[nt][2] + s[nt][3];
        }
        ls0 += __shfl_xor_sync(0xffffffffu, ls0, 1);
        ls0 += __shfl_xor_sync(0xffffffffu, ls0, 2);
        ls1 += __shfl_xor_sync(0xffffffffu, ls1, 1);
        ls1 += __shfl_xor_sync(0xffffffffu, ls1, 2);
        l0 = l0 * corr0 + ls0;
        l1 = l1 * corr1 + ls1;
#pragma unroll
        for (int nt = 0; nt < 4; nt++) {
            o[nt][0] *= corr0; o[nt][1] *= corr0;
            o[nt][2] *= corr1; o[nt][3] *= corr1;
        }

#pragma unroll
        for (int kt = 0; kt < 4; kt++) {
            uint32_t a0 = pack_bf16x2(s[2 * kt][0],     s[2 * kt][1]);
            uint32_t a1 = pack_bf16x2(s[2 * kt][2],     s[2 * kt][3]);
            uint32_t a2 = pack_bf16x2(s[2 * kt + 1][0], s[2 * kt + 1][1]);
            uint32_t a3 = pack_bf16x2(s[2 * kt + 1][2], s[2 * kt + 1][3]);
#pragma unroll
            for (int nt = 0; nt < 4; nt++) {
                uint32_t b0 = *(const uint32_t*)&Vt[nt * 8 + fr][kt * 16 + m2];
                uint32_t b1 = *(const uint32_t*)&Vt[nt * 8 + fr][kt * 16 + m2 + 8];
                mma_bf16(o[nt], a0, a1, a2, a3, b0, b1);
            }
        }
    }

    float inv0 = 1.f / l0, inv1 = 1.f / l1;
    int nr0 = n0 + r0, nr1 = nr0 + 8;
#pragma unroll
    for (int nt = 0; nt < 4; nt++) {
        int col = hg * DH + nt * 8 + m2;
        if (nr0 < NTOT)
            *(uint32_t*)&g_x12b[((size_t)b * NTOT + nr0) * CDIM + col] =
                pack_bf16x2(o[nt][0] * inv0, o[nt][1] * inv0);
        if (nr1 < NTOT)
            *(uint32_t*)&g_x12b[((size_t)b * NTOT + nr1) * CDIM + col] =
                pack_bf16x2(o[nt][2] * inv1, o[nt][3] * inv1);
    }
}

// ---------------------------------------------------------------------------
// Final projection + residual, split write to harness output.
// ---------------------------------------------------------------------------
__global__ void proj_kernel(const float* __restrict__ projb,
                            const float* __restrict__ resx, const float* __restrict__ resmsg,
                            float* __restrict__ out_img, float* __restrict__ out_msg) {
    __shared__ __nv_bfloat16 Xs[64][40];
    __shared__ __nv_bfloat16 Wsm[128][40];

    const int tid  = threadIdx.x;
    const int warp = tid >> 5;
    const int lane = tid & 31;
    const int mrow = (warp & 3) * 16;
    const int colBase = (warp >> 2) * 64;
    const int rowBase = blockIdx.x * 64;

    const int lrow = tid >> 2;
    const int koff = (tid & 3) * 8;
    const int gr = rowBase + lrow;
    const bool valid = gr < M_Q;
    const int fr = lane >> 2;
    const int m2 = (lane & 3) * 2;

    float c[8][4];
#pragma unroll
    for (int nt = 0; nt < 8; nt++) { c[nt][0] = c[nt][1] = c[nt][2] = c[nt][3] = 0.f; }

    for (int k0 = 0; k0 < CDIM; k0 += 32) {
        uint4 xv = make_uint4(0u, 0u, 0u, 0u);
        if (valid) xv = *(const uint4*)(g_x12b + (size_t)gr * CDIM + k0 + koff);
        *(uint4*)&Xs[lrow][koff] = xv;
        {
            const __nv_bfloat16* wp = g_projwb + (size_t)(tid >> 1) * CDIM + k0 + (tid & 1) * 16;
            *(uint4*)&Wsm[tid >> 1][(tid & 1) * 16]     = *(const uint4*)wp;
            *(uint4*)&Wsm[tid >> 1][(tid & 1) * 16 + 8] = *(const uint4*)(wp + 8);
        }
        __syncthreads();
#pragma unroll
        for (int kt = 0; kt < 2; kt++) {
            uint32_t a0 = *(const uint32_t*)&Xs[mrow + fr][kt * 16 + m2];
            uint32_t a1 = *(const uint32_t*)&Xs[mrow + fr + 8][kt * 16 + m2];
            uint32_t a2 = *(const uint32_t*)&Xs[mrow + fr][kt * 16 + m2 + 8];
            uint32_t a3 = *(const uint32_t*)&Xs[mrow + fr + 8][kt * 16 + m2 + 8];
#pragma unroll
            for (int nt = 0; nt < 8; nt++) {
                uint32_t b0 = *(const uint32_t*)&Wsm[colBase + nt * 8 + fr][kt * 16 + m2];
                uint32_t b1 = *(const uint32_t*)&Wsm[colBase + nt * 8 + fr][kt * 16 + m2 + 8];
                mma_bf16(c[nt], a0, a1, a2, a3, b0, b1);
            }
        }
        __syncthreads();
    }

    const int r0 = rowBase + mrow + fr;
    const int r1 = r0 + 8;
#pragma unroll
    for (int nt = 0; nt < 8; nt++) {
        int col = colBase + nt * 8 + m2;
        float bb0 = projb[col], bb1 = projb[col + 1];
        if (r0 < M_Q) {
            int b = r0 / NTOT, n = r0 - b * NTOT;
            if (n < N0) {
                size_t oo = ((size_t)b * N0 + n) * CDIM + col;
                *(float2*)&out_img[oo] = make_float2(c[nt][0] + bb0 + resx[oo],
                                                     c[nt][1] + bb1 + resx[oo + 1]);
            } else {
                size_t oo = ((size_t)b * NMSG + (n - N0)) * CDIM + col;
                *(float2*)&out_msg[oo] = make_float2(c[nt][0] + bb0 + resmsg[oo],
                                                     c[nt][1] + bb1 + resmsg[oo + 1]);
            }
        }
        if (r1 < M_Q) {
            int b = r1 / NTOT, n = r1 - b * NTOT;
            if (n < N0) {
                size_t oo = ((size_t)b * N0 + n) * CDIM + col;
                *(float2*)&out_img[oo] = make_float2(c[nt][2] + bb0 + resx[oo],
                                                     c[nt][3] + bb1 + resx[oo + 1]);
            } else {
                size_t oo = ((size_t)b * NMSG + (n - N0)) * CDIM + col;
                *(float2*)&out_msg[oo] = make_float2(c[nt][2] + bb0 + resmsg[oo],
                                                     c[nt][3] + bb1 + resmsg[oo + 1]);
            }
        }
    }
}

// ---------------------------------------------------------------------------
extern "C" void kernel_launch(void* const* d_in, const int* in_sizes, int n_in,
                              void* d_out, int out_size) {
    const float* x     = (const float*)d_in[0];
    const float* msg   = (const float*)d_in[1];
    const float* Wq    = (const float*)d_in[2];
    const float* bq    = (const float*)d_in[3];
    const float* sr1w  = (const float*)d_in[4];
    const float* sr1b  = (const float*)d_in[5];
    const float* ln1g  = (const float*)d_in[6];
    const float* ln1b  = (const float*)d_in[7];
    const float* sr2w  = (const float*)d_in[8];
    const float* sr2b  = (const float*)d_in[9];
    const float* ln2g  = (const float*)d_in[10];
    const float* ln2b  = (const float*)d_in[11];
    const float* kv1w  = (const float*)d_in[12];
    const float* kv1b  = (const float*)d_in[13];
    const float* kv2w  = (const float*)d_in[14];
    const float* kv2b  = (const float*)d_in[15];
    const float* lc1w  = (const float*)d_in[16];
    const float* lc1b  = (const float*)d_in[17];
    const float* lc2w  = (const float*)d_in[18];
    const float* lc2b  = (const float*)d_in[19];
    const float* projw = (const float*)d_in[20];
    const float* projb = (const float*)d_in[21];
    (void)in_sizes; (void)n_in; (void)out_size;

    float* out_img = (float*)d_out;
    float* out_msg = out_img + (size_t)BSZ * N0 * CDIM;

    // 1. all conversions / weight prep in one launch
    prep_kernel<<<PS9, 256>>>(x, msg, Wq, kv1w, kv2w, projw, sr1w, sr2w);

    // 2. Q + PATCH1(K-split x4) + PATCH2 GEMMs in one launch
    stage1_kernel<<<STAGE1_GRID, 256>>>(bq);

    // 3. partial-sum + SR bias + msg matvec + LN + GELU -> bf16
    lnfuse_kernel<<<M_KV1 + M_KV2, 128>>>(msg, sr1b, sr2b, ln1g, ln1b, ln2g, ln2b);

    // 4. KV projections (both branches); K->bf16, V->fp32
    kv_kernel<<<KV1_TILES + KV2_TILES, 256>>>(kv1b, kv2b);

    // 5. V augmentation -> bf16
    vmod_kernel<<<(M_KV1 + M_KV2 + 3) / 4, 256>>>(lc1w, lc1b, lc2w, lc2b);

    // 6. attention (both branches/heads), 128-q tiles, writes g_x12b
    {
        dim3 grid((NTOT + 127) / 128, 4, BSZ);
        attn_mma_kernel<<<grid, 256>>>();
    }

    // 7. output projection + residual, split write
    proj_kernel<<<NQ_TILES, 256>>>(projb, x, msg, out_img, out_msg);
}

// round 10
// speedup vs baseline: 6.4790x; 1.0053x over previous
#include <cuda_runtime.h>
#include <cuda_bf16.h>
#include <stdint.h>
#include <math.h>

#define BSZ   8
#define N0    4096
#define NMSG  4
#define NTOT  4100
#define CDIM  128
#define DH    32
#define ATT_SCALE 0.17677669529663687f  // 1/sqrt(32)

#define L1   256
#define LT1  260
#define HR1  16
#define WR1  16
#define L2   1024
#define LT2  1028
#define HR2  32
#define WR2  32

#define M_Q   (BSZ * NTOT)   // 32800
#define M_P1  (BSZ * L1)     // 2048
#define M_P2  (BSZ * L2)     // 8192
#define M_KV1 (BSZ * LT1)    // 2080
#define M_KV2 (BSZ * LT2)    // 8224

// stage1 grid layout
#define NQ_TILES  ((M_Q + 63) / 64)            // 513
#define P1_TILES  (M_P1 / 64)                  // 32
#define KSPLIT1   4
#define P1_BLKS   (P1_TILES * KSPLIT1)         // 128
#define P2_TILES  (M_P2 / 64)                  // 128
#define STAGE1_GRID (NQ_TILES + P1_BLKS + P2_TILES)

// kv grid
#define KV1_TILES ((M_KV1 + 63) / 64)          // 33
#define KV2_TILES ((M_KV2 + 63) / 64)          // 129

// ---------------- scratch (static device globals; no allocs) ----------------
__device__ float g_p1[KSPLIT1 * M_P1 * CDIM];  // PATCH1 K-split partials (no bias)
__device__ float g_p2[M_P2 * CDIM];            // PATCH2 output (no bias)
__device__ float g_v1f[M_KV1 * 64];            // V fp32 (pre-dwconv)
__device__ float g_v2f[M_KV2 * 64];
__device__ float g_ws1[CDIM * CDIM];           // transposed summed SR weights [c][o]
__device__ float g_ws2[CDIM * CDIM];

__device__ __nv_bfloat16 g_xb[BSZ * N0 * CDIM];
__device__ __nv_bfloat16 g_msgb[BSZ * NMSG * CDIM];
__device__ __nv_bfloat16 g_qb[M_Q * CDIM];     // Q (pre-scaled)
__device__ __nv_bfloat16 g_xk1b[M_KV1 * CDIM]; // post LN+GELU
__device__ __nv_bfloat16 g_xk2b[M_KV2 * CDIM];
__device__ __nv_bfloat16 g_k1b[M_KV1 * 64];    // K bf16
__device__ __nv_bfloat16 g_k2b[M_KV2 * 64];
__device__ __nv_bfloat16 g_v1mb[M_KV1 * 64];   // V + dwconv, bf16
__device__ __nv_bfloat16 g_v2mb[M_KV2 * 64];
__device__ __nv_bfloat16 g_x12b[M_Q * CDIM];   // attention outputs

__device__ __nv_bfloat16 g_wqb[CDIM * CDIM];
__device__ __nv_bfloat16 g_sr1wb[CDIM * CDIM * 16]; // [o][pos*128+c]
__device__ __nv_bfloat16 g_sr2wb[CDIM * CDIM * 4];
__device__ __nv_bfloat16 g_kv1wb[CDIM * CDIM];
__device__ __nv_bfloat16 g_kv2wb[CDIM * CDIM];
__device__ __nv_bfloat16 g_projwb[CDIM * CDIM];

// ---------------------------------------------------------------------------
__device__ __forceinline__ void mma_bf16(float c[4],
                                         uint32_t a0, uint32_t a1, uint32_t a2, uint32_t a3,
                                         uint32_t b0, uint32_t b1) {
    asm volatile(
        "mma.sync.aligned.m16n8k16.row.col.f32.bf16.bf16.f32 "
        "{%0,%1,%2,%3}, {%4,%5,%6,%7}, {%8,%9}, {%0,%1,%2,%3};"
        : "+f"(c[0]), "+f"(c[1]), "+f"(c[2]), "+f"(c[3])
        : "r"(a0), "r"(a1), "r"(a2), "r"(a3), "r"(b0), "r"(b1));
}

__device__ __forceinline__ uint32_t pack_bf16x2(float lo, float hi) {
    __nv_bfloat162 h = __floats2bfloat162_rn(lo, hi);
    return *reinterpret_cast<uint32_t*>(&h);
}

// ---------------------------------------------------------------------------
// prep: all fp32->bf16 conversions, SR weight reorder, summed-SR weights.
// ---------------------------------------------------------------------------
#define PS0 4096                  // xb (float4 per thread)
#define PS1 (PS0 + 16)            // msgb
#define PS2 (PS1 + 64)            // wqb
#define PS3 (PS2 + 64)            // kv1wb
#define PS4 (PS3 + 64)            // kv2wb
#define PS5 (PS4 + 64)            // projwb
#define PS6 (PS5 + 1024)          // wreorder sr1
#define PS7 (PS6 + 256)           // wreorder sr2
#define PS8 (PS7 + 64)            // wsum1
#define PS9 (PS8 + 64)            // wsum2   -> grid = PS9

__global__ void prep_kernel(const float* __restrict__ x,   const float* __restrict__ msg,
                            const float* __restrict__ Wq,  const float* __restrict__ kv1w,
                            const float* __restrict__ kv2w, const float* __restrict__ projw,
                            const float* __restrict__ sr1w, const float* __restrict__ sr2w) {
    int bid = blockIdx.x, t = threadIdx.x;
    if (bid < PS0) {
        int i = (bid * 256 + t) * 4;
        float4 v = *(const float4*)(x + i);
        __nv_bfloat16* o = g_xb + i;
        o[0] = __float2bfloat16(v.x); o[1] = __float2bfloat16(v.y);
        o[2] = __float2bfloat16(v.z); o[3] = __float2bfloat16(v.w);
    } else if (bid < PS1) {
        int i = (bid - PS0) * 256 + t;
        g_msgb[i] = __float2bfloat16(msg[i]);
    } else if (bid < PS2) {
        int i = (bid - PS1) * 256 + t;  g_wqb[i]   = __float2bfloat16(Wq[i]);
    } else if (bid < PS3) {
        int i = (bid - PS2) * 256 + t;  g_kv1wb[i] = __float2bfloat16(kv1w[i]);
    } else if (bid < PS4) {
        int i = (bid - PS3) * 256 + t;  g_kv2wb[i] = __float2bfloat16(kv2w[i]);
    } else if (bid < PS5) {
        int i = (bid - PS4) * 256 + t;  g_projwb[i] = __float2bfloat16(projw[i]);
    } else if (bid < PS6) {
        int idx = (bid - PS5) * 256 + t;          // [o][c][pos] src
        int o = idx >> 11;                         // / (128*16)
        int rem = idx & 2047;
        int cch = rem >> 4, pos = rem & 15;
        g_sr1wb[(size_t)o * 2048 + pos * CDIM + cch] = __float2bfloat16(sr1w[idx]);
    } else if (bid < PS7) {
        int idx = (bid - PS6) * 256 + t;
        int o = idx >> 9;                          // / (128*4)
        int rem = idx & 511;
        int cch = rem >> 2, pos = rem & 3;
        g_sr2wb[(size_t)o * 512 + pos * CDIM + cch] = __float2bfloat16(sr2w[idx]);
    } else if (bid < PS8) {
        int idx = (bid - PS7) * 256 + t;
        int c = idx >> 7, o = idx & 127;
        const float* p = sr1w + (o * CDIM + c) * 16;
        float s = 0.f;
#pragma unroll
        for (int i = 0; i < 16; i++) s += p[i];
        g_ws1[c * CDIM + o] = s;
    } else {
        int idx = (bid - PS8) * 256 + t;
        int c = idx >> 7, o = idx & 127;
        const float* p = sr2w + (o * CDIM + c) * 4;
        float s = 0.f;
#pragma unroll
        for (int i = 0; i < 4; i++) s += p[i];
        g_ws2[c * CDIM + o] = s;
    }
}

// ---------------------------------------------------------------------------
// stage1: Q projection + both SR patch-embed GEMMs in ONE launch.
// ---------------------------------------------------------------------------
__global__ void stage1_kernel(const float* __restrict__ bq) {
    __shared__ __nv_bfloat16 Xs[64][40];
    __shared__ __nv_bfloat16 Wsm[128][40];

    const int tid  = threadIdx.x;
    const int warp = tid >> 5;
    const int lane = tid & 31;
    const int mrow = (warp & 3) * 16;
    const int colBase = (warp >> 2) * 64;
    const int bid = blockIdx.x;

    int mode, S = 4, rowBase, K, kbase = 0, KTOT, M, Lloc = L1;
    const __nv_bfloat16* Wb;
    float* outP = nullptr;
    if (bid < NQ_TILES) {
        mode = 0; rowBase = bid * 64; K = 128; KTOT = 128; M = M_Q; Wb = g_wqb;
    } else if (bid < NQ_TILES + P1_BLKS) {
        int q = bid - NQ_TILES;
        mode = 1; S = 4; Lloc = L1;
        rowBase = (q >> 2) * 64;
        int kseg = q & 3;
        K = 512; kbase = kseg * 512; KTOT = 2048; M = M_P1;
        Wb = g_sr1wb; outP = g_p1 + (size_t)kseg * M_P1 * CDIM;
    } else {
        int q = bid - NQ_TILES - P1_BLKS;
        mode = 1; S = 2; Lloc = L2;
        rowBase = q * 64;
        K = 512; kbase = 0; KTOT = 512; M = M_P2;
        Wb = g_sr2wb; outP = g_p2;
    }

    const int lrow = tid >> 2;
    const int koff = (tid & 3) * 8;
    const int gr = rowBase + lrow;
    const bool valid = gr < M;

    const __nv_bfloat16* srcRow = nullptr;
    int pb = 0, phr = 0, pwr = 0;
    if (mode == 0) {
        if (valid) {
            int b = gr / NTOT, n = gr - b * NTOT;
            srcRow = (n < N0) ? g_xb + ((size_t)b * N0 + n) * CDIM
                              : g_msgb + ((size_t)b * NMSG + (n - N0)) * CDIM;
        }
    } else {
        if (valid) {
            pb = gr / Lloc; int l = gr - pb * Lloc;
            int Wr = (S == 4) ? WR1 : WR2;
            phr = l / Wr; pwr = l - phr * Wr;
        }
    }

    const int fr = lane >> 2;
    const int m2 = (lane & 3) * 2;

    float c[8][4];
#pragma unroll
    for (int nt = 0; nt < 8; nt++) { c[nt][0] = c[nt][1] = c[nt][2] = c[nt][3] = 0.f; }

    for (int k0 = 0; k0 < K; k0 += 32) {
        uint4 xv = make_uint4(0u, 0u, 0u, 0u);
        if (valid) {
            if (mode == 1) {
                int gk = kbase + k0;
                int pos = gk >> 7;
                int ky = (S == 4) ? (pos >> 2) : (pos >> 1);
                int kx = (S == 4) ? (pos & 3)  : (pos & 1);
                int p = (phr * S + ky) * 64 + pwr * S + kx;
                xv = *(const uint4*)(g_xb + ((size_t)pb * N0 + p) * CDIM + (gk & 127) + koff);
            } else {
                xv = *(const uint4*)(srcRow + k0 + koff);
            }
        }
        *(uint4*)&Xs[lrow][koff] = xv;
        {
            const __nv_bfloat16* wp = Wb + (size_t)(tid >> 1) * KTOT + kbase + k0 + (tid & 1) * 16;
            *(uint4*)&Wsm[tid >> 1][(tid & 1) * 16]     = *(const uint4*)wp;
            *(uint4*)&Wsm[tid >> 1][(tid & 1) * 16 + 8] = *(const uint4*)(wp + 8);
        }
        __syncthreads();

#pragma unroll
        for (int kt = 0; kt < 2; kt++) {
            uint32_t a0 = *(const uint32_t*)&Xs[mrow + fr][kt * 16 + m2];
            uint32_t a1 = *(const uint32_t*)&Xs[mrow + fr + 8][kt * 16 + m2];
            uint32_t a2 = *(const uint32_t*)&Xs[mrow + fr][kt * 16 + m2 + 8];
            uint32_t a3 = *(const uint32_t*)&Xs[mrow + fr + 8][kt * 16 + m2 + 8];
#pragma unroll
            for (int nt = 0; nt < 8; nt++) {
                uint32_t b0 = *(const uint32_t*)&Wsm[colBase + nt * 8 + fr][kt * 16 + m2];
                uint32_t b1 = *(const uint32_t*)&Wsm[colBase + nt * 8 + fr][kt * 16 + m2 + 8];
                mma_bf16(c[nt], a0, a1, a2, a3, b0, b1);
            }
        }
        __syncthreads();
    }

    const int r0 = rowBase + mrow + fr;
    const int r1 = r0 + 8;
#pragma unroll
    for (int nt = 0; nt < 8; nt++) {
        int col = colBase + nt * 8 + m2;
        if (mode == 0) {
            float bb0 = bq[col], bb1 = bq[col + 1];
            if (r0 < M) *(uint32_t*)&g_qb[(size_t)r0 * CDIM + col] =
                pack_bf16x2((c[nt][0] + bb0) * ATT_SCALE, (c[nt][1] + bb1) * ATT_SCALE);
            if (r1 < M) *(uint32_t*)&g_qb[(size_t)r1 * CDIM + col] =
                pack_bf16x2((c[nt][2] + bb0) * ATT_SCALE, (c[nt][3] + bb1) * ATT_SCALE);
        } else {
            if (r0 < M) *(float2*)&outP[(size_t)r0 * CDIM + col] = make_float2(c[nt][0], c[nt][1]);
            if (r1 < M) *(float2*)&outP[(size_t)r1 * CDIM + col] = make_float2(c[nt][2], c[nt][3]);
        }
    }
}

// ---------------------------------------------------------------------------
// LN+GELU fused: sums PATCH partials (+SR bias), msg-token SR matvec, LN+GELU.
// ---------------------------------------------------------------------------
__global__ void lnfuse_kernel(const float* __restrict__ msg,
                              const float* __restrict__ sr1b, const float* __restrict__ sr2b,
                              const float* __restrict__ ln1g, const float* __restrict__ ln1b,
                              const float* __restrict__ ln2g, const float* __restrict__ ln2b) {
    __shared__ float sm1[4], sm2[4];
    __shared__ float mrow[CDIM];
    int bid = blockIdx.x;
    int t = threadIdx.x, w = t >> 5, lane = t & 31;

    int br, b, l;
    if (bid < M_KV1) { br = 0; b = bid / LT1; l = bid - b * LT1; }
    else { int r2 = bid - M_KV1; br = 1; b = r2 / LT2; l = r2 - b * LT2; }

    const int Lloc = br ? L2 : L1;
    float v;
    if (l < Lloc) {
        if (br == 0) {
            size_t o = ((size_t)b * L1 + l) * CDIM + t;
            v = g_p1[o] + g_p1[(size_t)M_P1 * CDIM + o] + g_p1[(size_t)2 * M_P1 * CDIM + o]
              + g_p1[(size_t)3 * M_P1 * CDIM + o] + sr1b[t];
        } else {
            v = g_p2[((size_t)b * L2 + l) * CDIM + t] + sr2b[t];
        }
    } else {
        int n = l - Lloc;
        mrow[t] = msg[((size_t)b * NMSG + n) * CDIM + t];
        __syncthreads();
        const float* wsT = br ? g_ws2 : g_ws1;
        float a0 = 0.f, a1 = 0.f, a2 = 0.f, a3 = 0.f;
#pragma unroll 8
        for (int cc = 0; cc < CDIM; cc += 4) {
            a0 += mrow[cc + 0] * wsT[(cc + 0) * CDIM + t];
            a1 += mrow[cc + 1] * wsT[(cc + 1) * CDIM + t];
            a2 += mrow[cc + 2] * wsT[(cc + 2) * CDIM + t];
            a3 += mrow[cc + 3] * wsT[(cc + 3) * CDIM + t];
        }
        v = (a0 + a1) + (a2 + a3) + (br ? sr2b[t] : sr1b[t]);
    }
    __syncthreads();

    float s1 = v, s2 = v * v;
#pragma unroll
    for (int off = 16; off > 0; off >>= 1) {
        s1 += __shfl_xor_sync(0xffffffffu, s1, off);
        s2 += __shfl_xor_sync(0xffffffffu, s2, off);
    }
    if (lane == 0) { sm1[w] = s1; sm2[w] = s2; }
    __syncthreads();
    s1 = (sm1[0] + sm1[1]) + (sm1[2] + sm1[3]);
    s2 = (sm2[0] + sm2[1]) + (sm2[2] + sm2[3]);
    float mu  = s1 * (1.f / 128.f);
    float var = fmaxf(s2 * (1.f / 128.f) - mu * mu, 0.f);
    const float* g  = br ? ln2g : ln1g;
    const float* be = br ? ln2b : ln1b;
    float y = (v - mu) * rsqrtf(var + 1e-5f) * g[t] + be[t];
    float gel = 0.5f * y * (1.f + erff(y * 0.70710678118654752f));
    __nv_bfloat16* ob = br ? g_xk2b : g_xk1b;
    size_t row = br ? ((size_t)b * LT2 + l) : ((size_t)b * LT1 + l);
    ob[row * CDIM + t] = __float2bfloat16(gel);
}

// ---------------------------------------------------------------------------
// KV projections, both branches. K half -> bf16, V half -> fp32.
// ---------------------------------------------------------------------------
__global__ void kv_kernel(const float* __restrict__ kv1b_, const float* __restrict__ kv2b_) {
    __shared__ __nv_bfloat16 Xs[64][40];
    __shared__ __nv_bfloat16 Wsm[128][40];

    const int tid  = threadIdx.x;
    const int warp = tid >> 5;
    const int lane = tid & 31;
    const int mrow = (warp & 3) * 16;
    const int colBase = (warp >> 2) * 64;
    const int bid = blockIdx.x;

    int rowBase, M;
    const __nv_bfloat16 *Ab, *Wb;
    const float* bias;
    __nv_bfloat16* kb;
    float* vf;
    if (bid < KV1_TILES) {
        rowBase = bid * 64; M = M_KV1;
        Ab = g_xk1b; Wb = g_kv1wb; bias = kv1b_; kb = g_k1b; vf = g_v1f;
    } else {
        rowBase = (bid - KV1_TILES) * 64; M = M_KV2;
        Ab = g_xk2b; Wb = g_kv2wb; bias = kv2b_; kb = g_k2b; vf = g_v2f;
    }

    const int lrow = tid >> 2;
    const int koff = (tid & 3) * 8;
    const int gr = rowBase + lrow;
    const bool valid = gr < M;
    const int fr = lane >> 2;
    const int m2 = (lane & 3) * 2;

    float c[8][4];
#pragma unroll
    for (int nt = 0; nt < 8; nt++) { c[nt][0] = c[nt][1] = c[nt][2] = c[nt][3] = 0.f; }

    for (int k0 = 0; k0 < CDIM; k0 += 32) {
        uint4 xv = make_uint4(0u, 0u, 0u, 0u);
        if (valid) xv = *(const uint4*)(Ab + (size_t)gr * CDIM + k0 + koff);
        *(uint4*)&Xs[lrow][koff] = xv;
        {
            const __nv_bfloat16* wp = Wb + (size_t)(tid >> 1) * CDIM + k0 + (tid & 1) * 16;
            *(uint4*)&Wsm[tid >> 1][(tid & 1) * 16]     = *(const uint4*)wp;
            *(uint4*)&Wsm[tid >> 1][(tid & 1) * 16 + 8] = *(const uint4*)(wp + 8);
        }
        __syncthreads();
#pragma unroll
        for (int kt = 0; kt < 2; kt++) {
            uint32_t a0 = *(const uint32_t*)&Xs[mrow + fr][kt * 16 + m2];
            uint32_t a1 = *(const uint32_t*)&Xs[mrow + fr + 8][kt * 16 + m2];
            uint32_t a2 = *(const uint32_t*)&Xs[mrow + fr][kt * 16 + m2 + 8];
            uint32_t a3 = *(const uint32_t*)&Xs[mrow + fr + 8][kt * 16 + m2 + 8];
#pragma unroll
            for (int nt = 0; nt < 8; nt++) {
                uint32_t b0 = *(const uint32_t*)&Wsm[colBase + nt * 8 + fr][kt * 16 + m2];
                uint32_t b1 = *(const uint32_t*)&Wsm[colBase + nt * 8 + fr][kt * 16 + m2 + 8];
                mma_bf16(c[nt], a0, a1, a2, a3, b0, b1);
            }
        }
        __syncthreads();
    }

    const int r0 = rowBase + mrow + fr;
    const int r1 = r0 + 8;
#pragma unroll
    for (int nt = 0; nt < 8; nt++) {
        int col = colBase + nt * 8 + m2;
        float bb0 = bias[col], bb1 = bias[col + 1];
        float v00 = c[nt][0] + bb0, v01 = c[nt][1] + bb1;
        float v10 = c[nt][2] + bb0, v11 = c[nt][3] + bb1;
        if (col < 64) {  // K -> bf16
            if (r0 < M) *(uint32_t*)&kb[(size_t)r0 * 64 + col] = pack_bf16x2(v00, v01);
            if (r1 < M) *(uint32_t*)&kb[(size_t)r1 * 64 + col] = pack_bf16x2(v10, v11);
        } else {         // V -> fp32
            int vc = col - 64;
            if (r0 < M) *(float2*)&vf[(size_t)r0 * 64 + vc] = make_float2(v00, v01);
            if (r1 < M) *(float2*)&vf[(size_t)r1 * 64 + vc] = make_float2(v10, v11);
        }
    }
}

// ---------------------------------------------------------------------------
// v_mod both branches. bf16 out.
// ---------------------------------------------------------------------------
__global__ void vmod_kernel(const float* __restrict__ lw1, const float* __restrict__ lb1,
                            const float* __restrict__ lw2, const float* __restrict__ lb2) {
    int tid = threadIdx.x;
    int ch = tid & 63;
    int row = blockIdx.x * 4 + (tid >> 6);
    if (row >= M_KV1 + M_KV2) return;

    int b, l, Hr, Wr, Lloc, Lt;
    const float *vf, *lw, *lb;
    __nv_bfloat16* vm;
    if (row < M_KV1) {
        b = row / LT1; l = row - b * LT1;
        Hr = HR1; Wr = WR1; Lloc = L1; Lt = LT1;
        vf = g_v1f; lw = lw1; lb = lb1; vm = g_v1mb;
    } else {
        int r2 = row - M_KV1;
        b = r2 / LT2; l = r2 - b * LT2;
        Hr = HR2; Wr = WR2; Lloc = L2; Lt = LT2;
        vf = g_v2f; lw = lw2; lb = lb2; vm = g_v2mb;
    }
    float self = vf[((size_t)b * Lt + l) * 64 + ch];
    float o;
    if (l < Lloc) {
        int hr = l / Wr, wr = l - hr * Wr;
        float acc = lb[ch];
#pragma unroll
        for (int dy = 0; dy < 3; dy++) {
#pragma unroll
            for (int dx = 0; dx < 3; dx++) {
                int yy = hr + dy - 1, xx = wr + dx - 1;
                if (yy >= 0 && yy < Hr && xx >= 0 && xx < Wr)
                    acc += lw[ch * 9 + dy * 3 + dx] *
                           vf[((size_t)b * Lt + yy * Wr + xx) * 64 + ch];
            }
        }
        o = self + acc;
    } else {
        o = 2.f * self;
    }
    vm[((size_t)b * Lt + l) * 64 + ch] = __float2bfloat16(o);
}

// ---------------------------------------------------------------------------
// bf16 flash attention: 128-query tiles, 8 warps, double-buffered K/V smem
// (1 sync per 64-key chunk, prefetch overlapped with MMA), Vt stride 66
// (conflict-free transpose stores). Writes g_x12b directly.
// ---------------------------------------------------------------------------
#define VTS 66
__global__ void attn_mma_kernel() {
    __shared__ __nv_bfloat16 Qs[128][40];
    __shared__ __nv_bfloat16 Ks[2][64][40];
    __shared__ __nv_bfloat16 Vt[2][32][VTS];   // V transposed [d][key]

    const int tid  = threadIdx.x;
    const int warp = tid >> 5;
    const int lane = tid & 31;
    const int qt = blockIdx.x, hg = blockIdx.y, b = blockIdx.z;
    const int br = hg >> 1, hh = hg & 1;
    const __nv_bfloat16* kb = br ? g_k2b : g_k1b;
    const __nv_bfloat16* vm = br ? g_v2mb : g_v1mb;
    const int Lt = br ? LT2 : LT1;
    const int n0 = qt * 128;

    const int lr   = tid >> 2;         // 0..63 (load row)
    const int lkof = (tid & 3) * 8;    // 0/8/16/24 (load d-offset)

    // Q tile: 128 rows x 32 d
#pragma unroll
    for (int pass = 0; pass < 2; pass++) {
        int r = lr + pass * 64;
        int n = n0 + r;
        uint4 v = make_uint4(0u, 0u, 0u, 0u);
        if (n < NTOT)
            v = *(const uint4*)(g_qb + ((size_t)b * NTOT + n) * CDIM + hg * DH + lkof);
        *(uint4*)&Qs[r][lkof] = v;
    }

    // preload chunk 0 into buffer 0
    {
        uint4 kv4 = make_uint4(0u, 0u, 0u, 0u);
        uint4 vv4 = make_uint4(0u, 0u, 0u, 0u);
        if (lr < Lt) {
            size_t base = ((size_t)b * Lt + lr) * 64 + hh * DH + lkof;
            kv4 = *(const uint4*)(kb + base);
            vv4 = *(const uint4*)(vm + base);
        }
        *(uint4*)&Ks[0][lr][lkof] = kv4;
        const __nv_bfloat16* vb = (const __nv_bfloat16*)&vv4;
#pragma unroll
        for (int j = 0; j < 8; j++) Vt[0][lkof + j][lr] = vb[j];
    }
    __syncthreads();

    const int fr = lane >> 2;
    const int m2 = (lane & 3) * 2;
    const int r0 = warp * 16 + fr;

    uint32_t qa[2][4];
#pragma unroll
    for (int kt = 0; kt < 2; kt++) {
        qa[kt][0] = *(const uint32_t*)&Qs[r0][kt * 16 + m2];
        qa[kt][1] = *(const uint32_t*)&Qs[r0 + 8][kt * 16 + m2];
        qa[kt][2] = *(const uint32_t*)&Qs[r0][kt * 16 + m2 + 8];
        qa[kt][3] = *(const uint32_t*)&Qs[r0 + 8][kt * 16 + m2 + 8];
    }

    float o[4][4];
#pragma unroll
    for (int i = 0; i < 4; i++)
#pragma unroll
        for (int j = 0; j < 4; j++) o[i][j] = 0.f;
    float m0 = -1e30f, m1 = -1e30f, l0 = 0.f, l1 = 0.f;

    const int nc = (Lt + 63) >> 6;
    for (int ci = 0; ci < nc; ci++) {
        const int c0 = ci << 6;
        const int buf = ci & 1;
        const bool pf = (ci + 1) < nc;

        // prefetch next chunk into registers (latency hidden behind MMAs)
        uint4 kv4n = make_uint4(0u, 0u, 0u, 0u);
        uint4 vv4n = make_uint4(0u, 0u, 0u, 0u);
        if (pf) {
            int gl = c0 + 64 + lr;
            if (gl < Lt) {
                size_t base = ((size_t)b * Lt + gl) * 64 + hh * DH + lkof;
                kv4n = *(const uint4*)(kb + base);
                vv4n = *(const uint4*)(vm + base);
            }
        }

        float s[8][4];
#pragma unroll
        for (int nt = 0; nt < 8; nt++) { s[nt][0] = s[nt][1] = s[nt][2] = s[nt][3] = 0.f; }
#pragma unroll
        for (int nt = 0; nt < 8; nt++) {
#pragma unroll
            for (int kt = 0; kt < 2; kt++) {
                uint32_t b0 = *(const uint32_t*)&Ks[buf][nt * 8 + fr][kt * 16 + m2];
                uint32_t b1 = *(const uint32_t*)&Ks[buf][nt * 8 + fr][kt * 16 + m2 + 8];
                mma_bf16(s[nt], qa[kt][0], qa[kt][1], qa[kt][2], qa[kt][3], b0, b1);
            }
        }

        float mx0 = m0, mx1 = m1;
#pragma unroll
        for (int nt = 0; nt < 8; nt++) {
            int gc = c0 + nt * 8 + m2;
            if (gc >= Lt)     { s[nt][0] = -1e30f; s[nt][2] = -1e30f; }
            if (gc + 1 >= Lt) { s[nt][1] = -1e30f; s[nt][3] = -1e30f; }
            mx0 = fmaxf(mx0, fmaxf(s[nt][0], s[nt][1]));
            mx1 = fmaxf(mx1, fmaxf(s[nt][2], s[nt][3]));
        }
        mx0 = fmaxf(mx0, __shfl_xor_sync(0xffffffffu, mx0, 1));
        mx0 = fmaxf(mx0, __shfl_xor_sync(0xffffffffu, mx0, 2));
        mx1 = fmaxf(mx1, __shfl_xor_sync(0xffffffffu, mx1, 1));
        mx1 = fmaxf(mx1, __shfl_xor_sync(0xffffffffu, mx1, 2));
        float corr0 = __expf(m0 - mx0), corr1 = __expf(m1 - mx1);
        m0 = mx0; m1 = mx1;

        float ls0 = 0.f, ls1 = 0.f;
#pragma unroll
        for (int nt = 0; nt < 8; nt++) {
            s[nt][0] = __expf(s[nt][0] - m0);
            s[nt][1] = __expf(s[nt][1] - m0);
            s[nt][2] = __expf(s[nt][2] - m1);
            s[nt][3] = __expf(s[nt][3] - m1);
            ls0 += s[nt][0] + s[nt][1];
            ls1 += s[nt][2] + s[nt][3];
        }
        ls0 += __shfl_xor_sync(0xffffffffu, ls0, 1);
        ls0 += __shfl_xor_sync(0xffffffffu, ls0, 2);
        ls1 += __shfl_xor_sync(0xffffffffu, ls1, 1);
        ls1 += __shfl_xor_sync(0xffffffffu, ls1, 2);
        l0 = l0 * corr0 + ls0;
        l1 = l1 * corr1 + ls1;
#pragma unroll
        for (int nt = 0; nt < 4; nt++) {
            o[nt][0] *= corr0; o[nt][1] *= corr0;
            o[nt][2] *= corr1; o[nt][3] *= corr1;
        }

#pragma unroll
        for (int kt = 0; kt < 4; kt++) {
            uint32_t a0 = pack_bf16x2(s[2 * kt][0],     s[2 * kt][1]);
            uint32_t a1 = pack_bf16x2(s[2 * kt][2],     s[2 * kt][3]);
            uint32_t a2 = pack_bf16x2(s[2 * kt + 1][0], s[2 * kt + 1][1]);
            uint32_t a3 = pack_bf16x2(s[2 * kt + 1][2], s[2 * kt + 1][3]);
#pragma unroll
            for (int nt = 0; nt < 4; nt++) {
                uint32_t b0 = *(const uint32_t*)&Vt[buf][nt * 8 + fr][kt * 16 + m2];
                uint32_t b1 = *(const uint32_t*)&Vt[buf][nt * 8 + fr][kt * 16 + m2 + 8];
                mma_bf16(o[nt], a0, a1, a2, a3, b0, b1);
            }
        }

        // store prefetched chunk into the other buffer (no race: different buf;
        // prior readers of buf^1 passed the previous sync)
        if (pf) {
            *(uint4*)&Ks[buf ^ 1][lr][lkof] = kv4n;
            const __nv_bfloat16* vb = (const __nv_bfloat16*)&vv4n;
#pragma unroll
            for (int j = 0; j < 8; j++) Vt[buf ^ 1][lkof + j][lr] = vb[j];
        }
        __syncthreads();
    }

    float inv0 = 1.f / l0, inv1 = 1.f / l1;
    int nr0 = n0 + r0, nr1 = nr0 + 8;
#pragma unroll
    for (int nt = 0; nt < 4; nt++) {
        int col = hg * DH + nt * 8 + m2;
        if (nr0 < NTOT)
            *(uint32_t*)&g_x12b[((size_t)b * NTOT + nr0) * CDIM + col] =
                pack_bf16x2(o[nt][0] * inv0, o[nt][1] * inv0);
        if (nr1 < NTOT)
            *(uint32_t*)&g_x12b[((size_t)b * NTOT + nr1) * CDIM + col] =
                pack_bf16x2(o[nt][2] * inv1, o[nt][3] * inv1);
    }
}

// ---------------------------------------------------------------------------
// Final projection + residual, split write to harness output.
// ---------------------------------------------------------------------------
__global__ void proj_kernel(const float* __restrict__ projb,
                            const float* __restrict__ resx, const float* __restrict__ resmsg,
                            float* __restrict__ out_img, float* __restrict__ out_msg) {
    __shared__ __nv_bfloat16 Xs[64][40];
    __shared__ __nv_bfloat16 Wsm[128][40];

    const int tid  = threadIdx.x;
    const int warp = tid >> 5;
    const int lane = tid & 31;
    const int mrow = (warp & 3) * 16;
    const int colBase = (warp >> 2) * 64;
    const int rowBase = blockIdx.x * 64;

    const int lrow = tid >> 2;
    const int koff = (tid & 3) * 8;
    const int gr = rowBase + lrow;
    const bool valid = gr < M_Q;
    const int fr = lane >> 2;
    const int m2 = (lane & 3) * 2;

    float c[8][4];
#pragma unroll
    for (int nt = 0; nt < 8; nt++) { c[nt][0] = c[nt][1] = c[nt][2] = c[nt][3] = 0.f; }

    for (int k0 = 0; k0 < CDIM; k0 += 32) {
        uint4 xv = make_uint4(0u, 0u, 0u, 0u);
        if (valid) xv = *(const uint4*)(g_x12b + (size_t)gr * CDIM + k0 + koff);
        *(uint4*)&Xs[lrow][koff] = xv;
        {
            const __nv_bfloat16* wp = g_projwb + (size_t)(tid >> 1) * CDIM + k0 + (tid & 1) * 16;
            *(uint4*)&Wsm[tid >> 1][(tid & 1) * 16]     = *(const uint4*)wp;
            *(uint4*)&Wsm[tid >> 1][(tid & 1) * 16 + 8] = *(const uint4*)(wp + 8);
        }
        __syncthreads();
#pragma unroll
        for (int kt = 0; kt < 2; kt++) {
            uint32_t a0 = *(const uint32_t*)&Xs[mrow + fr][kt * 16 + m2];
            uint32_t a1 = *(const uint32_t*)&Xs[mrow + fr + 8][kt * 16 + m2];
            uint32_t a2 = *(const uint32_t*)&Xs[mrow + fr][kt * 16 + m2 + 8];
            uint32_t a3 = *(const uint32_t*)&Xs[mrow + fr + 8][kt * 16 + m2 + 8];
#pragma unroll
            for (int nt = 0; nt < 8; nt++) {
                uint32_t b0 = *(const uint32_t*)&Wsm[colBase + nt * 8 + fr][kt * 16 + m2];
                uint32_t b1 = *(const uint32_t*)&Wsm[colBase + nt * 8 + fr][kt * 16 + m2 + 8];
                mma_bf16(c[nt], a0, a1, a2, a3, b0, b1);
            }
        }
        __syncthreads();
    }

    const int r0 = rowBase + mrow + fr;
    const int r1 = r0 + 8;
#pragma unroll
    for (int nt = 0; nt < 8; nt++) {
        int col = colBase + nt * 8 + m2;
        float bb0 = projb[col], bb1 = projb[col + 1];
        if (r0 < M_Q) {
            int b = r0 / NTOT, n = r0 - b * NTOT;
            if (n < N0) {
                size_t oo = ((size_t)b * N0 + n) * CDIM + col;
                *(float2*)&out_img[oo] = make_float2(c[nt][0] + bb0 + resx[oo],
                                                     c[nt][1] + bb1 + resx[oo + 1]);
            } else {
                size_t oo = ((size_t)b * NMSG + (n - N0)) * CDIM + col;
                *(float2*)&out_msg[oo] = make_float2(c[nt][0] + bb0 + resmsg[oo],
                                                     c[nt][1] + bb1 + resmsg[oo + 1]);
            }
        }
        if (r1 < M_Q) {
            int b = r1 / NTOT, n = r1 - b * NTOT;
            if (n < N0) {
                size_t oo = ((size_t)b * N0 + n) * CDIM + col;
                *(float2*)&out_img[oo] = make_float2(c[nt][2] + bb0 + resx[oo],
                                                     c[nt][3] + bb1 + resx[oo + 1]);
            } else {
                size_t oo = ((size_t)b * NMSG + (n - N0)) * CDIM + col;
                *(float2*)&out_msg[oo] = make_float2(c[nt][2] + bb0 + resmsg[oo],
                                                     c[nt][3] + bb1 + resmsg[oo + 1]);
            }
        }
    }
}

// ---------------------------------------------------------------------------
extern "C" void kernel_launch(void* const* d_in, const int* in_sizes, int n_in,
                              void* d_out, int out_size) {
    const float* x     = (const float*)d_in[0];
    const float* msg   = (const float*)d_in[1];
    const float* Wq    = (const float*)d_in[2];
    const float* bq    = (const float*)d_in[3];
    const float* sr1w  = (const float*)d_in[4];
    const float* sr1b  = (const float*)d_in[5];
    const float* ln1g  = (const float*)d_in[6];
    const float* ln1b  = (const float*)d_in[7];
    const float* sr2w  = (const float*)d_in[8];
    const float* sr2b  = (const float*)d_in[9];
    const float* ln2g  = (const float*)d_in[10];
    const float* ln2b  = (const float*)d_in[11];
    const float* kv1w  = (const float*)d_in[12];
    const float* kv1b  = (const float*)d_in[13];
    const float* kv2w  = (const float*)d_in[14];
    const float* kv2b  = (const float*)d_in[15];
    const float* lc1w  = (const float*)d_in[16];
    const float* lc1b  = (const float*)d_in[17];
    const float* lc2w  = (const float*)d_in[18];
    const float* lc2b  = (const float*)d_in[19];
    const float* projw = (const float*)d_in[20];
    const float* projb = (const float*)d_in[21];
    (void)in_sizes; (void)n_in; (void)out_size;

    float* out_img = (float*)d_out;
    float* out_msg = out_img + (size_t)BSZ * N0 * CDIM;

    // 1. all conversions / weight prep in one launch
    prep_kernel<<<PS9, 256>>>(x, msg, Wq, kv1w, kv2w, projw, sr1w, sr2w);

    // 2. Q + PATCH1(K-split x4) + PATCH2 GEMMs in one launch
    stage1_kernel<<<STAGE1_GRID, 256>>>(bq);

    // 3. partial-sum + SR bias + msg matvec + LN + GELU -> bf16
    lnfuse_kernel<<<M_KV1 + M_KV2, 128>>>(msg, sr1b, sr2b, ln1g, ln1b, ln2g, ln2b);

    // 4. KV projections (both branches); K->bf16, V->fp32
    kv_kernel<<<KV1_TILES + KV2_TILES, 256>>>(kv1b, kv2b);

    // 5. V augmentation -> bf16
    vmod_kernel<<<(M_KV1 + M_KV2 + 3) / 4, 256>>>(lc1w, lc1b, lc2w, lc2b);

    // 6. attention (both branches/heads), double-buffered, writes g_x12b
    {
        dim3 grid((NTOT + 127) / 128, 4, BSZ);
        attn_mma_kernel<<<grid, 256>>>();
    }

    // 7. output projection + residual, split write
    proj_kernel<<<NQ_TILES, 256>>>(projb, x, msg, out_img, out_msg);
}